// round 8
// baseline (speedup 1.0000x reference)
#include <cuda_runtime.h>
#include <math.h>

#define BATCH 2
#define HH 256
#define WW 256
#define CIN 64
#define HEADS 8
#define HD 512

// ---------------- scratch (device globals; no runtime allocation) ----------------
__device__ float g_S[BATCH * 64 * 64];        // xd^T xd per batch
__device__ float g_SQ[BATCH * 64 * HD];       // S @ Wq
__device__ float g_nk[BATCH * HD];
__device__ float g_nq[BATCH * HD];
__device__ float g_M[BATCH * 64 * 64];        // Wv @ A^T @ Wproj per batch
__device__ float g_Wp[64 * 64];               // Wv @ Wc1d
__device__ float g_P[(size_t)BATCH * HH * WW * 64];  // p_pre (33.5 MB)

// ---------------- K0: zero accumulated buffers ----------------
__global__ void k0_zero() {
    int i = blockIdx.x * blockDim.x + threadIdx.x;
    if (i < BATCH * 4096) { g_S[i] = 0.f; g_M[i] = 0.f; }
    if (i < 4096) g_Wp[i] = 0.f;
}

// ---------------- K1: S_b = xd^T xd, xd = avgpool2x2(x) ----------------
// grid 64: 32 blocks/batch, each owns 4 ds-rows (512 tokens)
__global__ void k1_S(const float* __restrict__ x) {
    __shared__ float xs[16 * 64];
    int b  = blockIdx.x >> 5;
    int r0 = (blockIdx.x & 31) * 4;
    int tid = threadIdx.x;
    int ti = tid >> 4, tj = tid & 15;
    float acc[4][4];
#pragma unroll
    for (int r = 0; r < 4; r++)
#pragma unroll
        for (int s = 0; s < 4; s++) acc[r][s] = 0.f;

    int c   = tid & 63;
    int tl0 = tid >> 6;  // 0..3
    for (int g = 0; g < 32; g++) {
        int row  = r0 + (g >> 3);
        int col0 = (g & 7) * 16;
#pragma unroll
        for (int it = 0; it < 4; it++) {
            int tl = it * 4 + tl0;
            int gx = (col0 + tl) * 2;
            int gy = row * 2;
            const float* p0 = x + (((size_t)b * HH + gy) * WW + gx) * 64 + c;
            xs[tl * 64 + c] = 0.25f * (p0[0] + p0[64] + p0[WW * 64] + p0[WW * 64 + 64]);
        }
        __syncthreads();
#pragma unroll
        for (int t = 0; t < 16; t++) {
            float4 av = *(const float4*)&xs[t * 64 + 4 * ti];
            float4 bv = *(const float4*)&xs[t * 64 + 4 * tj];
            float a4[4] = {av.x, av.y, av.z, av.w};
            float b4[4] = {bv.x, bv.y, bv.z, bv.w};
#pragma unroll
            for (int r = 0; r < 4; r++)
#pragma unroll
                for (int s = 0; s < 4; s++) acc[r][s] += a4[r] * b4[s];
        }
        __syncthreads();
    }
    float* Sb = g_S + b * 4096;
#pragma unroll
    for (int r = 0; r < 4; r++)
#pragma unroll
        for (int s = 0; s < 4; s++)
            atomicAdd(&Sb[(4 * ti + r) * 64 + 4 * tj + s], acc[r][s]);
}

// ---------------- K2: SQ = S@Wq (stored), norms nk/nq ----------------
// grid 16: (b, h)
__global__ void k2_SQ(const float* __restrict__ Wq, const float* __restrict__ Wk) {
    __shared__ float Ss[4096];
    __shared__ float Wc[4096];
    __shared__ float n2[64];
    int b = blockIdx.x >> 3, h = blockIdx.x & 7;
    int tid = threadIdx.x, ti = tid >> 4, tj = tid & 15;
    for (int u = tid; u < 4096; u += 256) Ss[u] = g_S[b * 4096 + u];

    for (int pass = 0; pass < 2; pass++) {
        const float* Wsrc = pass ? Wk : Wq;
        for (int u = tid; u < 4096; u += 256) {
            int cc = u >> 6, j = u & 63;
            Wc[u] = Wsrc[cc * HD + h * 64 + j];
        }
        if (tid < 64) n2[tid] = 0.f;
        __syncthreads();

        float acc[4][4];
#pragma unroll
        for (int r = 0; r < 4; r++)
#pragma unroll
            for (int s = 0; s < 4; s++) acc[r][s] = 0.f;
#pragma unroll 16
        for (int cc = 0; cc < 64; cc++) {
            float4 bv = *(const float4*)&Wc[cc * 64 + 4 * tj];
            float b4[4] = {bv.x, bv.y, bv.z, bv.w};
            float a4[4];
#pragma unroll
            for (int r = 0; r < 4; r++) a4[r] = Ss[(4 * ti + r) * 64 + cc];
#pragma unroll
            for (int r = 0; r < 4; r++)
#pragma unroll
                for (int s = 0; s < 4; s++) acc[r][s] += a4[r] * b4[s];
        }
        float psum[4] = {0.f, 0.f, 0.f, 0.f};
#pragma unroll
        for (int r = 0; r < 4; r++)
#pragma unroll
            for (int s = 0; s < 4; s++)
                psum[s] += Wc[(4 * ti + r) * 64 + 4 * tj + s] * acc[r][s];
        if (!pass) {
#pragma unroll
            for (int r = 0; r < 4; r++)
#pragma unroll
                for (int s = 0; s < 4; s++)
                    g_SQ[b * 32768 + (4 * ti + r) * HD + h * 64 + 4 * tj + s] = acc[r][s];
        }
#pragma unroll
        for (int s = 0; s < 4; s++) atomicAdd(&n2[4 * tj + s], psum[s]);
        __syncthreads();
        if (tid < 64) {
            float nv = fmaxf(sqrtf(fmaxf(n2[tid], 0.f)), 1e-12f);
            (pass ? g_nk : g_nq)[b * HD + h * 64 + tid] = nv;
        }
        __syncthreads();
    }
}

// ---------------- K3: attn -> M_b, and Wp = Wv@Wc1d ----------------
// grid 16: (b, h), dynamic smem = (12288 + 128) floats
__global__ void k3_attn(const float* __restrict__ Wk, const float* __restrict__ Wq,
                        const float* __restrict__ rescale, const float* __restrict__ Wproj,
                        const float* __restrict__ Wv, const float* __restrict__ Wc1d) {
    extern __shared__ float sm3[];
    float* bufA = sm3;
    float* bufB = sm3 + 4096;
    float* bufC = sm3 + 8192;
    float* nks  = sm3 + 12288;
    float* nqs  = nks + 64;
    int b = blockIdx.x >> 3, h = blockIdx.x & 7;
    int tid = threadIdx.x, ti = tid >> 4, tj = tid & 15;

    for (int u = tid; u < 4096; u += 256) {
        int cc = u >> 6, i = u & 63;
        bufA[u] = Wk[cc * HD + h * 64 + i];              // Wk_h [c][i]
        bufB[u] = g_SQ[b * 32768 + cc * HD + h * 64 + i]; // SQ_h [c][j]
    }
    if (tid < 64) { nks[tid] = g_nk[b * HD + h * 64 + tid]; nqs[tid] = g_nq[b * HD + h * 64 + tid]; }
    __syncthreads();
    float resc = rescale[h];

    float acc[4][4];
#pragma unroll
    for (int r = 0; r < 4; r++)
#pragma unroll
        for (int s = 0; s < 4; s++) acc[r][s] = 0.f;
#pragma unroll 16
    for (int cc = 0; cc < 64; cc++) {   // G[i][j] = sum_c Wk_h[c][i] * SQ_h[c][j]
        float4 av = *(const float4*)&bufA[cc * 64 + 4 * ti];
        float4 bv = *(const float4*)&bufB[cc * 64 + 4 * tj];
        float a4[4] = {av.x, av.y, av.z, av.w}, b4[4] = {bv.x, bv.y, bv.z, bv.w};
#pragma unroll
        for (int r = 0; r < 4; r++)
#pragma unroll
            for (int s = 0; s < 4; s++) acc[r][s] += a4[r] * b4[s];
    }
#pragma unroll
    for (int r = 0; r < 4; r++)
#pragma unroll
        for (int s = 0; s < 4; s++)
            bufC[(4 * ti + r) * 64 + 4 * tj + s] =
                acc[r][s] / (nks[4 * ti + r] * nqs[4 * tj + s]) * resc;
    __syncthreads();

    // overwrite bufA with Wproj_h [i][d]; softmax rows of bufC concurrently
    for (int u = tid; u < 4096; u += 256)
        bufA[u] = Wproj[(h * 64 + (u >> 6)) * 64 + (u & 63)];
    if (tid < 64) {
        float m = -1e30f;
        for (int j = 0; j < 64; j++) m = fmaxf(m, bufC[tid * 64 + j]);
        float ss = 0.f;
        for (int j = 0; j < 64; j++) { float e = expf(bufC[tid * 64 + j] - m); bufC[tid * 64 + j] = e; ss += e; }
        float inv = 1.f / ss;
        for (int j = 0; j < 64; j++) bufC[tid * 64 + j] *= inv;
    }
    __syncthreads();

    // B[j][d] = sum_i attn[i][j] * Wproj_h[i][d]   (into regs, then bufB)
#pragma unroll
    for (int r = 0; r < 4; r++)
#pragma unroll
        for (int s = 0; s < 4; s++) acc[r][s] = 0.f;
#pragma unroll 16
    for (int i = 0; i < 64; i++) {
        float4 av = *(const float4*)&bufC[i * 64 + 4 * ti];   // j = 4ti+r
        float4 bv = *(const float4*)&bufA[i * 64 + 4 * tj];   // d = 4tj+s
        float a4[4] = {av.x, av.y, av.z, av.w}, b4[4] = {bv.x, bv.y, bv.z, bv.w};
#pragma unroll
        for (int r = 0; r < 4; r++)
#pragma unroll
            for (int s = 0; s < 4; s++) acc[r][s] += a4[r] * b4[s];
    }
    __syncthreads();   // everyone done reading bufB (G stage long done), bufC reads done
#pragma unroll
    for (int r = 0; r < 4; r++)
#pragma unroll
        for (int s = 0; s < 4; s++) bufB[(4 * ti + r) * 64 + 4 * tj + s] = acc[r][s];
    for (int u = tid; u < 4096; u += 256)
        bufC[u] = Wv[(u >> 6) * HD + h * 64 + (u & 63)];      // Wv_h [c][j]
    __syncthreads();

    // C[c][d] = sum_j Wv_h[c][j] * B[j][d] -> atomic into g_M[b]
#pragma unroll
    for (int r = 0; r < 4; r++)
#pragma unroll
        for (int s = 0; s < 4; s++) acc[r][s] = 0.f;
#pragma unroll 16
    for (int j = 0; j < 64; j++) {
        float4 bv = *(const float4*)&bufB[j * 64 + 4 * tj];
        float b4[4] = {bv.x, bv.y, bv.z, bv.w};
        float a4[4];
#pragma unroll
        for (int r = 0; r < 4; r++) a4[r] = bufC[(4 * ti + r) * 64 + j];
#pragma unroll
        for (int r = 0; r < 4; r++)
#pragma unroll
            for (int s = 0; s < 4; s++) acc[r][s] += a4[r] * b4[s];
    }
#pragma unroll
    for (int r = 0; r < 4; r++)
#pragma unroll
        for (int s = 0; s < 4; s++)
            atomicAdd(&g_M[b * 4096 + (4 * ti + r) * 64 + 4 * tj + s], acc[r][s]);

    if (b == 0) {  // Wp = Wv @ Wc1d (batch independent): blocks of batch 0 only
        __syncthreads();
        for (int u = tid; u < 4096; u += 256)
            bufA[u] = Wc1d[(h * 64 + (u >> 6)) * 64 + (u & 63)];  // [j][d]
        __syncthreads();
#pragma unroll
        for (int r = 0; r < 4; r++)
#pragma unroll
            for (int s = 0; s < 4; s++) acc[r][s] = 0.f;
#pragma unroll 16
        for (int j = 0; j < 64; j++) {
            float4 bv = *(const float4*)&bufA[j * 64 + 4 * tj];
            float b4[4] = {bv.x, bv.y, bv.z, bv.w};
            float a4[4];
#pragma unroll
            for (int r = 0; r < 4; r++) a4[r] = bufC[(4 * ti + r) * 64 + j];
#pragma unroll
            for (int r = 0; r < 4; r++)
#pragma unroll
                for (int s = 0; s < 4; s++) acc[r][s] += a4[r] * b4[s];
        }
#pragma unroll
        for (int r = 0; r < 4; r++)
#pragma unroll
            for (int s = 0; s < 4; s++)
                atomicAdd(&g_Wp[(4 * ti + r) * 64 + 4 * tj + s], acc[r][s]);
    }
}

// ---------------- K4a: p_pre = x @ Wp + bc1d -> g_P ----------------
// grid 2048 blocks x 64 pixels
__global__ void k4a_P(const float* __restrict__ x, const float* __restrict__ bc1d) {
    __shared__ float Wps[4096];
    __shared__ float xs[4096];
    __shared__ float bc[64];
    int tid = threadIdx.x;
    for (int u = tid; u < 4096; u += 256) Wps[u] = g_Wp[u];
    if (tid < 64) bc[tid] = bc1d[tid];
    size_t base = (size_t)blockIdx.x * 4096;
    const float4* src = (const float4*)(x + base);
    for (int u = tid; u < 1024; u += 256) ((float4*)xs)[u] = src[u];
    __syncthreads();

    int ti = tid >> 4, tj = tid & 15;
    float acc[4][4];
#pragma unroll
    for (int r = 0; r < 4; r++)
#pragma unroll
        for (int s = 0; s < 4; s++) acc[r][s] = 0.f;
#pragma unroll 16
    for (int cc = 0; cc < 64; cc++) {
        float4 bv = *(const float4*)&Wps[cc * 64 + 4 * tj];
        float b4[4] = {bv.x, bv.y, bv.z, bv.w};
        float a4[4];
#pragma unroll
        for (int r = 0; r < 4; r++) a4[r] = xs[(4 * ti + r) * 64 + cc];
#pragma unroll
        for (int r = 0; r < 4; r++)
#pragma unroll
            for (int s = 0; s < 4; s++) acc[r][s] += a4[r] * b4[s];
    }
#pragma unroll
    for (int r = 0; r < 4; r++) {
        float4 o;
        o.x = acc[r][0] + bc[4 * tj + 0];
        o.y = acc[r][1] + bc[4 * tj + 1];
        o.z = acc[r][2] + bc[4 * tj + 2];
        o.w = acc[r][3] + bc[4 * tj + 3];
        *(float4*)(g_P + base + (size_t)(4 * ti + r) * 64 + 4 * tj) = o;
    }
}

// ---------------- K4b: conv1+GELU+conv2 + x@M + bproj -> out ----------------
// grid 2048: (b, 32x32 tiles of 8x8). dyn smem = 25024 floats
__global__ void k4b_main(const float* __restrict__ x, const float* __restrict__ bproj,
                         const float* __restrict__ Wpe1, const float* __restrict__ Wpe2,
                         float* __restrict__ out) {
    extern __shared__ float sm4[];
    float* ps  = sm4;          // 12x12x64 = 9216
    float* p1  = ps + 9216;    // 10x10x64 = 6400
    float* xs  = p1 + 6400;    // 8x8x64   = 4096
    float* Ms  = xs + 4096;    // 4096
    float* w1  = Ms + 4096;    // 576
    float* w2  = w1 + 576;     // 576
    float* bps = w2 + 576;     // 64
    int blk = blockIdx.x;
    int b = blk >> 10;
    int rem = blk & 1023;
    int y0 = (rem >> 5) * 8, x0 = (rem & 31) * 8;
    int tid = threadIdx.x;

    for (int u = tid; u < 4096; u += 256) Ms[u] = g_M[b * 4096 + u];
    for (int u = tid; u < 576; u += 256) { w1[u] = Wpe1[u]; w2[u] = Wpe2[u]; }
    if (tid < 64) bps[tid] = bproj[tid];
    for (int u = tid; u < 1024; u += 256) {  // interior x tile (8 rows x 512 floats)
        int py = u >> 7, off = u & 127;
        const float4* src = (const float4*)(x + (((size_t)(b * HH + y0 + py)) * WW + x0) * 64);
        ((float4*)xs)[py * 128 + off] = src[off];
    }
    for (int u = tid; u < 9216; u += 256) {  // halo p_pre with zero pad
        int px = u >> 6, c = u & 63;
        int py = px / 12, pxx = px - py * 12;
        int gy = y0 - 2 + py, gx = x0 - 2 + pxx;
        float v = 0.f;
        if ((unsigned)gy < HH && (unsigned)gx < WW)
            v = g_P[(((size_t)(b * HH + gy)) * WW + gx) * 64 + c];
        ps[u] = v;
    }
    __syncthreads();

    for (int u = tid; u < 6400; u += 256) {  // conv1 + exact GELU, zero outside image
        int px = u >> 6, c = u & 63;
        int py = px / 10, pxx = px - py * 10;
        int gy = y0 - 1 + py, gx = x0 - 1 + pxx;
        float v = 0.f;
        if ((unsigned)gy < HH && (unsigned)gx < WW) {
            float a = 0.f;
#pragma unroll
            for (int ky = 0; ky < 3; ky++)
#pragma unroll
                for (int kx = 0; kx < 3; kx++)
                    a += ps[((py + ky) * 12 + pxx + kx) * 64 + c] * w1[c * 9 + ky * 3 + kx];
            v = 0.5f * a * (1.f + erff(a * 0.70710678118654752f));
        }
        p1[u] = v;
    }
    __syncthreads();

    int ti = tid >> 4, tj = tid & 15;
    float wr[4][9];
#pragma unroll
    for (int s = 0; s < 4; s++)
#pragma unroll
        for (int k = 0; k < 9; k++) wr[s][k] = w2[(4 * tj + s) * 9 + k];

    float acc[4][4];
#pragma unroll
    for (int r = 0; r < 4; r++)
#pragma unroll
        for (int s = 0; s < 4; s++) acc[r][s] = 0.f;
#pragma unroll 16
    for (int cc = 0; cc < 64; cc++) {        // x @ M
        float4 bv = *(const float4*)&Ms[cc * 64 + 4 * tj];
        float b4[4] = {bv.x, bv.y, bv.z, bv.w};
        float a4[4];
#pragma unroll
        for (int r = 0; r < 4; r++) a4[r] = xs[(4 * ti + r) * 64 + cc];
#pragma unroll
        for (int r = 0; r < 4; r++)
#pragma unroll
            for (int s = 0; s < 4; s++) acc[r][s] += a4[r] * b4[s];
    }
#pragma unroll
    for (int r = 0; r < 4; r++) {            // conv2 + combine + store
        int pl = 4 * ti + r, py = pl >> 3, pxx = pl & 7;
        float cv[4] = {0.f, 0.f, 0.f, 0.f};
#pragma unroll
        for (int ky = 0; ky < 3; ky++)
#pragma unroll
            for (int kx = 0; kx < 3; kx++) {
                int k = ky * 3 + kx;
                float4 pv = *(const float4*)&p1[((py + ky) * 10 + pxx + kx) * 64 + 4 * tj];
                cv[0] += pv.x * wr[0][k];
                cv[1] += pv.y * wr[1][k];
                cv[2] += pv.z * wr[2][k];
                cv[3] += pv.w * wr[3][k];
            }
        float4 o;
        o.x = acc[r][0] + cv[0] + bps[4 * tj + 0];
        o.y = acc[r][1] + cv[1] + bps[4 * tj + 1];
        o.z = acc[r][2] + cv[2] + bps[4 * tj + 2];
        o.w = acc[r][3] + cv[3] + bps[4 * tj + 3];
        *(float4*)(out + (((size_t)(b * HH + y0 + py)) * WW + x0 + pxx) * 64 + 4 * tj) = o;
    }
}

// ---------------- launch ----------------
extern "C" void kernel_launch(void* const* d_in, const int* in_sizes, int n_in,
                              void* d_out, int out_size) {
    const float* x     = (const float*)d_in[0];
    const float* Wq    = (const float*)d_in[1];
    const float* Wk    = (const float*)d_in[2];
    const float* Wv    = (const float*)d_in[3];
    const float* resc  = (const float*)d_in[4];
    const float* Wproj = (const float*)d_in[5];
    const float* bproj = (const float*)d_in[6];
    const float* Wc1d  = (const float*)d_in[7];
    const float* bc1d  = (const float*)d_in[8];
    const float* Wpe1  = (const float*)d_in[9];
    const float* Wpe2  = (const float*)d_in[10];
    float* out = (float*)d_out;

    cudaFuncSetAttribute(k3_attn, cudaFuncAttributeMaxDynamicSharedMemorySize, (12288 + 128) * 4);
    cudaFuncSetAttribute(k4b_main, cudaFuncAttributeMaxDynamicSharedMemorySize, 25024 * 4);

    k0_zero<<<32, 256>>>();
    k1_S<<<64, 256>>>(x);
    k2_SQ<<<16, 256>>>(Wq, Wk);
    k3_attn<<<16, 256, (12288 + 128) * 4>>>(Wk, Wq, resc, Wproj, Wv, Wc1d);
    k4a_P<<<2048, 256>>>(x, bc1d);
    k4b_main<<<2048, 256, 25024 * 4>>>(x, bproj, Wpe1, Wpe2, out);
}

// round 9
// speedup vs baseline: 1.0380x; 1.0380x over previous
#include <cuda_runtime.h>
#include <math.h>

#define BATCH 2
#define HH 256
#define WW 256
#define CIN 64
#define HEADS 8
#define HD 512

// ---------------- scratch (device globals; no runtime allocation) ----------------
__device__ float g_S[BATCH * 64 * 64];        // xd^T xd per batch
__device__ float g_SQ[BATCH * 64 * HD];       // S @ Wq
__device__ float g_nk[BATCH * HD];
__device__ float g_nq[BATCH * HD];
__device__ float g_M[BATCH * 64 * 64];        // Wv @ A^T @ Wproj per batch
__device__ float g_Wp[64 * 64];               // Wv @ Wc1d
__device__ float g_P[(size_t)BATCH * HH * WW * 64];  // p_pre (33.5 MB)

// ---------------- K0: zero accumulated buffers ----------------
__global__ void k0_zero() {
    int i = blockIdx.x * blockDim.x + threadIdx.x;
    if (i < BATCH * 4096) { g_S[i] = 0.f; g_M[i] = 0.f; }
    if (i < 4096) g_Wp[i] = 0.f;
}

// ---------------- K1: S_b = xd^T xd, xd = avgpool2x2(x) ----------------
// grid 64: 32 blocks/batch, each owns 4 ds-rows (512 tokens)
__global__ void k1_S(const float* __restrict__ x) {
    __shared__ float xs[16 * 64];
    int b  = blockIdx.x >> 5;
    int r0 = (blockIdx.x & 31) * 4;
    int tid = threadIdx.x;
    int ti = tid >> 4, tj = tid & 15;
    float acc[4][4];
#pragma unroll
    for (int r = 0; r < 4; r++)
#pragma unroll
        for (int s = 0; s < 4; s++) acc[r][s] = 0.f;

    int c   = tid & 63;
    int tl0 = tid >> 6;  // 0..3
    for (int g = 0; g < 32; g++) {
        int row  = r0 + (g >> 3);
        int col0 = (g & 7) * 16;
#pragma unroll
        for (int it = 0; it < 4; it++) {
            int tl = it * 4 + tl0;
            int gx = (col0 + tl) * 2;
            int gy = row * 2;
            const float* p0 = x + (((size_t)b * HH + gy) * WW + gx) * 64 + c;
            xs[tl * 64 + c] = 0.25f * (p0[0] + p0[64] + p0[WW * 64] + p0[WW * 64 + 64]);
        }
        __syncthreads();
#pragma unroll
        for (int t = 0; t < 16; t++) {
            float4 av = *(const float4*)&xs[t * 64 + 4 * ti];
            float4 bv = *(const float4*)&xs[t * 64 + 4 * tj];
            float a4[4] = {av.x, av.y, av.z, av.w};
            float b4[4] = {bv.x, bv.y, bv.z, bv.w};
#pragma unroll
            for (int r = 0; r < 4; r++)
#pragma unroll
                for (int s = 0; s < 4; s++) acc[r][s] += a4[r] * b4[s];
        }
        __syncthreads();
    }
    float* Sb = g_S + b * 4096;
#pragma unroll
    for (int r = 0; r < 4; r++)
#pragma unroll
        for (int s = 0; s < 4; s++)
            atomicAdd(&Sb[(4 * ti + r) * 64 + 4 * tj + s], acc[r][s]);
}

// ---------------- K2: SQ = S@Wq (stored), norms nk/nq ----------------
// grid 16: (b, h)
__global__ void k2_SQ(const float* __restrict__ Wq, const float* __restrict__ Wk) {
    __shared__ float Ss[4096];
    __shared__ float Wc[4096];
    __shared__ float n2[64];
    int b = blockIdx.x >> 3, h = blockIdx.x & 7;
    int tid = threadIdx.x, ti = tid >> 4, tj = tid & 15;
    for (int u = tid; u < 4096; u += 256) Ss[u] = g_S[b * 4096 + u];

    for (int pass = 0; pass < 2; pass++) {
        const float* Wsrc = pass ? Wk : Wq;
        for (int u = tid; u < 4096; u += 256) {
            int cc = u >> 6, j = u & 63;
            Wc[u] = Wsrc[cc * HD + h * 64 + j];
        }
        if (tid < 64) n2[tid] = 0.f;
        __syncthreads();

        float acc[4][4];
#pragma unroll
        for (int r = 0; r < 4; r++)
#pragma unroll
            for (int s = 0; s < 4; s++) acc[r][s] = 0.f;
#pragma unroll 16
        for (int cc = 0; cc < 64; cc++) {
            float4 bv = *(const float4*)&Wc[cc * 64 + 4 * tj];
            float b4[4] = {bv.x, bv.y, bv.z, bv.w};
            float a4[4];
#pragma unroll
            for (int r = 0; r < 4; r++) a4[r] = Ss[(4 * ti + r) * 64 + cc];
#pragma unroll
            for (int r = 0; r < 4; r++)
#pragma unroll
                for (int s = 0; s < 4; s++) acc[r][s] += a4[r] * b4[s];
        }
        float psum[4] = {0.f, 0.f, 0.f, 0.f};
#pragma unroll
        for (int r = 0; r < 4; r++)
#pragma unroll
            for (int s = 0; s < 4; s++)
                psum[s] += Wc[(4 * ti + r) * 64 + 4 * tj + s] * acc[r][s];
        if (!pass) {
#pragma unroll
            for (int r = 0; r < 4; r++)
#pragma unroll
                for (int s = 0; s < 4; s++)
                    g_SQ[b * 32768 + (4 * ti + r) * HD + h * 64 + 4 * tj + s] = acc[r][s];
        }
#pragma unroll
        for (int s = 0; s < 4; s++) atomicAdd(&n2[4 * tj + s], psum[s]);
        __syncthreads();
        if (tid < 64) {
            float nv = fmaxf(sqrtf(fmaxf(n2[tid], 0.f)), 1e-12f);
            (pass ? g_nk : g_nq)[b * HD + h * 64 + tid] = nv;
        }
        __syncthreads();
    }
}

// ---------------- K3: attn -> M_b, and Wp = Wv@Wc1d ----------------
// grid 16: (b, h), dynamic smem = (12288 + 128) floats
__global__ void k3_attn(const float* __restrict__ Wk, const float* __restrict__ Wq,
                        const float* __restrict__ rescale, const float* __restrict__ Wproj,
                        const float* __restrict__ Wv, const float* __restrict__ Wc1d) {
    extern __shared__ float sm3[];
    float* bufA = sm3;
    float* bufB = sm3 + 4096;
    float* bufC = sm3 + 8192;
    float* nks  = sm3 + 12288;
    float* nqs  = nks + 64;
    int b = blockIdx.x >> 3, h = blockIdx.x & 7;
    int tid = threadIdx.x, ti = tid >> 4, tj = tid & 15;

    for (int u = tid; u < 4096; u += 256) {
        int cc = u >> 6, i = u & 63;
        bufA[u] = Wk[cc * HD + h * 64 + i];              // Wk_h [c][i]
        bufB[u] = g_SQ[b * 32768 + cc * HD + h * 64 + i]; // SQ_h [c][j]
    }
    if (tid < 64) { nks[tid] = g_nk[b * HD + h * 64 + tid]; nqs[tid] = g_nq[b * HD + h * 64 + tid]; }
    __syncthreads();
    float resc = rescale[h];

    float acc[4][4];
#pragma unroll
    for (int r = 0; r < 4; r++)
#pragma unroll
        for (int s = 0; s < 4; s++) acc[r][s] = 0.f;
#pragma unroll 16
    for (int cc = 0; cc < 64; cc++) {   // G[i][j] = sum_c Wk_h[c][i] * SQ_h[c][j]
        float4 av = *(const float4*)&bufA[cc * 64 + 4 * ti];
        float4 bv = *(const float4*)&bufB[cc * 64 + 4 * tj];
        float a4[4] = {av.x, av.y, av.z, av.w}, b4[4] = {bv.x, bv.y, bv.z, bv.w};
#pragma unroll
        for (int r = 0; r < 4; r++)
#pragma unroll
            for (int s = 0; s < 4; s++) acc[r][s] += a4[r] * b4[s];
    }
#pragma unroll
    for (int r = 0; r < 4; r++)
#pragma unroll
        for (int s = 0; s < 4; s++)
            bufC[(4 * ti + r) * 64 + 4 * tj + s] =
                acc[r][s] / (nks[4 * ti + r] * nqs[4 * tj + s]) * resc;
    __syncthreads();

    // overwrite bufA with Wproj_h [i][d]; softmax rows of bufC concurrently
    for (int u = tid; u < 4096; u += 256)
        bufA[u] = Wproj[(h * 64 + (u >> 6)) * 64 + (u & 63)];
    if (tid < 64) {
        float m = -1e30f;
        for (int j = 0; j < 64; j++) m = fmaxf(m, bufC[tid * 64 + j]);
        float ss = 0.f;
        for (int j = 0; j < 64; j++) { float e = expf(bufC[tid * 64 + j] - m); bufC[tid * 64 + j] = e; ss += e; }
        float inv = 1.f / ss;
        for (int j = 0; j < 64; j++) bufC[tid * 64 + j] *= inv;
    }
    __syncthreads();

    // B[j][d] = sum_i attn[i][j] * Wproj_h[i][d]   (into regs, then bufB)
#pragma unroll
    for (int r = 0; r < 4; r++)
#pragma unroll
        for (int s = 0; s < 4; s++) acc[r][s] = 0.f;
#pragma unroll 16
    for (int i = 0; i < 64; i++) {
        float4 av = *(const float4*)&bufC[i * 64 + 4 * ti];   // j = 4ti+r
        float4 bv = *(const float4*)&bufA[i * 64 + 4 * tj];   // d = 4tj+s
        float a4[4] = {av.x, av.y, av.z, av.w}, b4[4] = {bv.x, bv.y, bv.z, bv.w};
#pragma unroll
        for (int r = 0; r < 4; r++)
#pragma unroll
            for (int s = 0; s < 4; s++) acc[r][s] += a4[r] * b4[s];
    }
    __syncthreads();   // everyone done reading bufB (G stage long done), bufC reads done
#pragma unroll
    for (int r = 0; r < 4; r++)
#pragma unroll
        for (int s = 0; s < 4; s++) bufB[(4 * ti + r) * 64 + 4 * tj + s] = acc[r][s];
    for (int u = tid; u < 4096; u += 256)
        bufC[u] = Wv[(u >> 6) * HD + h * 64 + (u & 63)];      // Wv_h [c][j]
    __syncthreads();

    // C[c][d] = sum_j Wv_h[c][j] * B[j][d] -> atomic into g_M[b]
#pragma unroll
    for (int r = 0; r < 4; r++)
#pragma unroll
        for (int s = 0; s < 4; s++) acc[r][s] = 0.f;
#pragma unroll 16
    for (int j = 0; j < 64; j++) {
        float4 bv = *(const float4*)&bufB[j * 64 + 4 * tj];
        float b4[4] = {bv.x, bv.y, bv.z, bv.w};
        float a4[4];
#pragma unroll
        for (int r = 0; r < 4; r++) a4[r] = bufC[(4 * ti + r) * 64 + j];
#pragma unroll
        for (int r = 0; r < 4; r++)
#pragma unroll
            for (int s = 0; s < 4; s++) acc[r][s] += a4[r] * b4[s];
    }
#pragma unroll
    for (int r = 0; r < 4; r++)
#pragma unroll
        for (int s = 0; s < 4; s++)
            atomicAdd(&g_M[b * 4096 + (4 * ti + r) * 64 + 4 * tj + s], acc[r][s]);

    if (b == 0) {  // Wp = Wv @ Wc1d (batch independent): blocks of batch 0 only
        __syncthreads();
        for (int u = tid; u < 4096; u += 256)
            bufA[u] = Wc1d[(h * 64 + (u >> 6)) * 64 + (u & 63)];  // [j][d]
        __syncthreads();
#pragma unroll
        for (int r = 0; r < 4; r++)
#pragma unroll
            for (int s = 0; s < 4; s++) acc[r][s] = 0.f;
#pragma unroll 16
        for (int j = 0; j < 64; j++) {
            float4 bv = *(const float4*)&bufA[j * 64 + 4 * tj];
            float b4[4] = {bv.x, bv.y, bv.z, bv.w};
            float a4[4];
#pragma unroll
            for (int r = 0; r < 4; r++) a4[r] = bufC[(4 * ti + r) * 64 + j];
#pragma unroll
            for (int r = 0; r < 4; r++)
#pragma unroll
                for (int s = 0; s < 4; s++) acc[r][s] += a4[r] * b4[s];
        }
#pragma unroll
        for (int r = 0; r < 4; r++)
#pragma unroll
            for (int s = 0; s < 4; s++)
                atomicAdd(&g_Wp[(4 * ti + r) * 64 + 4 * tj + s], acc[r][s]);
    }
}

// ---------------- K4a: p_pre = x @ Wp + bc1d -> g_P ----------------
// grid 2048 blocks x 64 pixels
__global__ void k4a_P(const float* __restrict__ x, const float* __restrict__ bc1d) {
    __shared__ float Wps[4096];
    __shared__ float xs[4096];
    __shared__ float bc[64];
    int tid = threadIdx.x;
    for (int u = tid; u < 4096; u += 256) Wps[u] = g_Wp[u];
    if (tid < 64) bc[tid] = bc1d[tid];
    size_t base = (size_t)blockIdx.x * 4096;
    const float4* src = (const float4*)(x + base);
    for (int u = tid; u < 1024; u += 256) ((float4*)xs)[u] = src[u];
    __syncthreads();

    int ti = tid >> 4, tj = tid & 15;
    float acc[4][4];
#pragma unroll
    for (int r = 0; r < 4; r++)
#pragma unroll
        for (int s = 0; s < 4; s++) acc[r][s] = 0.f;
#pragma unroll 16
    for (int cc = 0; cc < 64; cc++) {
        float4 bv = *(const float4*)&Wps[cc * 64 + 4 * tj];
        float b4[4] = {bv.x, bv.y, bv.z, bv.w};
        float a4[4];
#pragma unroll
        for (int r = 0; r < 4; r++) a4[r] = xs[(4 * ti + r) * 64 + cc];
#pragma unroll
        for (int r = 0; r < 4; r++)
#pragma unroll
            for (int s = 0; s < 4; s++) acc[r][s] += a4[r] * b4[s];
    }
#pragma unroll
    for (int r = 0; r < 4; r++) {
        float4 o;
        o.x = acc[r][0] + bc[4 * tj + 0];
        o.y = acc[r][1] + bc[4 * tj + 1];
        o.z = acc[r][2] + bc[4 * tj + 2];
        o.w = acc[r][3] + bc[4 * tj + 3];
        *(float4*)(g_P + base + (size_t)(4 * ti + r) * 64 + 4 * tj) = o;
    }
}

// ---------------- K4b: conv1+GELU+conv2 + x@M + bproj -> out ----------------
// grid 2048: (b, 32x32 tiles of 8x8). dyn smem = 25024 floats
__global__ void k4b_main(const float* __restrict__ x, const float* __restrict__ bproj,
                         const float* __restrict__ Wpe1, const float* __restrict__ Wpe2,
                         float* __restrict__ out) {
    extern __shared__ float sm4[];
    float* ps  = sm4;          // 12x12x64 = 9216
    float* p1  = ps + 9216;    // 10x10x64 = 6400
    float* xs  = p1 + 6400;    // 8x8x64   = 4096
    float* Ms  = xs + 4096;    // 4096
    float* w1  = Ms + 4096;    // 576
    float* w2  = w1 + 576;     // 576
    float* bps = w2 + 576;     // 64
    int blk = blockIdx.x;
    int b = blk >> 10;
    int rem = blk & 1023;
    int y0 = (rem >> 5) * 8, x0 = (rem & 31) * 8;
    int tid = threadIdx.x;

    for (int u = tid; u < 4096; u += 256) Ms[u] = g_M[b * 4096 + u];
    for (int u = tid; u < 576; u += 256) { w1[u] = Wpe1[u]; w2[u] = Wpe2[u]; }
    if (tid < 64) bps[tid] = bproj[tid];
    for (int u = tid; u < 1024; u += 256) {  // interior x tile (8 rows x 512 floats)
        int py = u >> 7, off = u & 127;
        const float4* src = (const float4*)(x + (((size_t)(b * HH + y0 + py)) * WW + x0) * 64);
        ((float4*)xs)[py * 128 + off] = src[off];
    }
    for (int u = tid; u < 9216; u += 256) {  // halo p_pre with zero pad
        int px = u >> 6, c = u & 63;
        int py = px / 12, pxx = px - py * 12;
        int gy = y0 - 2 + py, gx = x0 - 2 + pxx;
        float v = 0.f;
        if ((unsigned)gy < HH && (unsigned)gx < WW)
            v = g_P[(((size_t)(b * HH + gy)) * WW + gx) * 64 + c];
        ps[u] = v;
    }
    __syncthreads();

    for (int u = tid; u < 6400; u += 256) {  // conv1 + exact GELU, zero outside image
        int px = u >> 6, c = u & 63;
        int py = px / 10, pxx = px - py * 10;
        int gy = y0 - 1 + py, gx = x0 - 1 + pxx;
        float v = 0.f;
        if ((unsigned)gy < HH && (unsigned)gx < WW) {
            float a = 0.f;
#pragma unroll
            for (int ky = 0; ky < 3; ky++)
#pragma unroll
                for (int kx = 0; kx < 3; kx++)
                    a += ps[((py + ky) * 12 + pxx + kx) * 64 + c] * w1[c * 9 + ky * 3 + kx];
            v = 0.5f * a * (1.f + erff(a * 0.70710678118654752f));
        }
        p1[u] = v;
    }
    __syncthreads();

    int ti = tid >> 4, tj = tid & 15;
    float wr[4][9];
#pragma unroll
    for (int s = 0; s < 4; s++)
#pragma unroll
        for (int k = 0; k < 9; k++) wr[s][k] = w2[(4 * tj + s) * 9 + k];

    float acc[4][4];
#pragma unroll
    for (int r = 0; r < 4; r++)
#pragma unroll
        for (int s = 0; s < 4; s++) acc[r][s] = 0.f;
#pragma unroll 16
    for (int cc = 0; cc < 64; cc++) {        // x @ M
        float4 bv = *(const float4*)&Ms[cc * 64 + 4 * tj];
        float b4[4] = {bv.x, bv.y, bv.z, bv.w};
        float a4[4];
#pragma unroll
        for (int r = 0; r < 4; r++) a4[r] = xs[(4 * ti + r) * 64 + cc];
#pragma unroll
        for (int r = 0; r < 4; r++)
#pragma unroll
            for (int s = 0; s < 4; s++) acc[r][s] += a4[r] * b4[s];
    }
#pragma unroll
    for (int r = 0; r < 4; r++) {            // conv2 + combine + store
        int pl = 4 * ti + r, py = pl >> 3, pxx = pl & 7;
        float cv[4] = {0.f, 0.f, 0.f, 0.f};
#pragma unroll
        for (int ky = 0; ky < 3; ky++)
#pragma unroll
            for (int kx = 0; kx < 3; kx++) {
                int k = ky * 3 + kx;
                float4 pv = *(const float4*)&p1[((py + ky) * 10 + pxx + kx) * 64 + 4 * tj];
                cv[0] += pv.x * wr[0][k];
                cv[1] += pv.y * wr[1][k];
                cv[2] += pv.z * wr[2][k];
                cv[3] += pv.w * wr[3][k];
            }
        float4 o;
        o.x = acc[r][0] + cv[0] + bps[4 * tj + 0];
        o.y = acc[r][1] + cv[1] + bps[4 * tj + 1];
        o.z = acc[r][2] + cv[2] + bps[4 * tj + 2];
        o.w = acc[r][3] + cv[3] + bps[4 * tj + 3];
        *(float4*)(out + (((size_t)(b * HH + y0 + py)) * WW + x0 + pxx) * 64 + 4 * tj) = o;
    }
}

// ---------------- launch ----------------
extern "C" void kernel_launch(void* const* d_in, const int* in_sizes, int n_in,
                              void* d_out, int out_size) {
    const float* x     = (const float*)d_in[0];
    const float* Wq    = (const float*)d_in[1];
    const float* Wk    = (const float*)d_in[2];
    const float* Wv    = (const float*)d_in[3];
    const float* resc  = (const float*)d_in[4];
    const float* Wproj = (const float*)d_in[5];
    const float* bproj = (const float*)d_in[6];
    const float* Wc1d  = (const float*)d_in[7];
    const float* bc1d  = (const float*)d_in[8];
    const float* Wpe1  = (const float*)d_in[9];
    const float* Wpe2  = (const float*)d_in[10];
    float* out = (float*)d_out;

    cudaFuncSetAttribute(k3_attn, cudaFuncAttributeMaxDynamicSharedMemorySize, (12288 + 128) * 4);
    cudaFuncSetAttribute(k4b_main, cudaFuncAttributeMaxDynamicSharedMemorySize, 25024 * 4);

    k0_zero<<<32, 256>>>();
    k1_S<<<64, 256>>>(x);
    k2_SQ<<<16, 256>>>(Wq, Wk);
    k3_attn<<<16, 256, (12288 + 128) * 4>>>(Wk, Wq, resc, Wproj, Wv, Wc1d);
    k4a_P<<<2048, 256>>>(x, bc1d);
    k4b_main<<<2048, 256, 25024 * 4>>>(x, bproj, Wpe1, Wpe2, out);
}

// round 11
// speedup vs baseline: 1.4910x; 1.4364x over previous
#include <cuda_runtime.h>
#include <math.h>

#define HH 256
#define WW 256
#define HD 512

// ---------------- scratch (device globals) ----------------
__device__ float g_S[2 * 4096];                      // xd^T xd per batch
__device__ float g_M[2 * 4096];                      // Wv @ A^T @ Wproj per batch
__device__ float g_Wp[4096];                         // Wv @ Wc1d
__device__ float g_P[(size_t)2 * HH * WW * 64];      // p_pre

// 4x4 outer-product micro-op: acc[s] += sum_k a.k * bk.s
__device__ __forceinline__ void mk44(float4 a, float4 b0, float4 b1, float4 b2, float4 b3,
                                     float* acc) {
    acc[0] += a.x * b0.x + a.y * b1.x + a.z * b2.x + a.w * b3.x;
    acc[1] += a.x * b0.y + a.y * b1.y + a.z * b2.y + a.w * b3.y;
    acc[2] += a.x * b0.z + a.y * b1.z + a.z * b2.z + a.w * b3.z;
    acc[3] += a.x * b0.w + a.y * b1.w + a.z * b2.w + a.w * b3.w;
}

// ---------------- K0: zero accumulators ----------------
__global__ void k0_zero() {
    int i = blockIdx.x * 1024 + threadIdx.x;
    if (i < 8192) { g_S[i] = 0.f; g_M[i] = 0.f; }
    if (i < 4096) g_Wp[i] = 0.f;
}

// ---------------- K1: S partials (blocks 0..127) + Wp partials (blocks 128..135) ----------------
__global__ void k1_S_Wp(const float* __restrict__ x, const float* __restrict__ Wv,
                        const float* __restrict__ Wc1d) {
    __shared__ float sm[8192];
    int blk = blockIdx.x, tid = threadIdx.x;
    if (blk < 128) {
        float* xs = sm;                       // 16 tokens x 64 ch
        int b = blk >> 6, rp = blk & 63;      // 2 ds-rows per block
        int ti = tid >> 4, tj = tid & 15;
        int c4 = (tid & 15) * 4;              // channel group for loading
        int tl = tid >> 4;                    // token lane for loading
        float acc[4][4];
#pragma unroll
        for (int r = 0; r < 4; r++)
#pragma unroll
            for (int s = 0; s < 4; s++) acc[r][s] = 0.f;

        for (int g = 0; g < 16; g++) {
            int dr = rp * 2 + (g >> 3);
            int dc = (g & 7) * 16 + tl;
            int gy = dr * 2, gx = dc * 2;
            const float* p0 = x + (((size_t)b * HH + gy) * WW + gx) * 64 + c4;
            float4 v0 = *(const float4*)p0;
            float4 v1 = *(const float4*)(p0 + 64);
            float4 v2 = *(const float4*)(p0 + WW * 64);
            float4 v3 = *(const float4*)(p0 + WW * 64 + 64);
            float4 s4;
            s4.x = 0.25f * (v0.x + v1.x + v2.x + v3.x);
            s4.y = 0.25f * (v0.y + v1.y + v2.y + v3.y);
            s4.z = 0.25f * (v0.z + v1.z + v2.z + v3.z);
            s4.w = 0.25f * (v0.w + v1.w + v2.w + v3.w);
            *(float4*)&xs[tl * 64 + c4] = s4;
            __syncthreads();
#pragma unroll
            for (int t = 0; t < 16; t++) {
                float4 av = *(const float4*)&xs[t * 64 + 4 * ti];
                float4 bv = *(const float4*)&xs[t * 64 + 4 * tj];
                float a4[4] = {av.x, av.y, av.z, av.w};
                float b4[4] = {bv.x, bv.y, bv.z, bv.w};
#pragma unroll
                for (int r = 0; r < 4; r++)
#pragma unroll
                    for (int s = 0; s < 4; s++) acc[r][s] += a4[r] * b4[s];
            }
            __syncthreads();
        }
        float* Sb = g_S + b * 4096;
#pragma unroll
        for (int r = 0; r < 4; r++)
#pragma unroll
            for (int s = 0; s < 4; s++)
                atomicAdd(&Sb[(4 * ti + r) * 64 + 4 * tj + s], acc[r][s]);
    } else {
        // Wp partial: f-slice [f0, f0+64)
        float* Av = sm;            // Wv[c][ff]
        float* Bv = sm + 4096;     // Wc1d[ff][d]
        int f0 = (blk - 128) * 64;
        for (int u = tid; u < 4096; u += 256) {
            Av[u] = Wv[(u >> 6) * HD + f0 + (u & 63)];
            Bv[u] = Wc1d[f0 * 64 + u];
        }
        __syncthreads();
        int ti = tid >> 4, tj = tid & 15;
        float acc[4][4];
#pragma unroll
        for (int r = 0; r < 4; r++)
#pragma unroll
            for (int s = 0; s < 4; s++) acc[r][s] = 0.f;
#pragma unroll
        for (int cc4 = 0; cc4 < 64; cc4 += 4) {
            float4 b0 = *(const float4*)&Bv[(cc4 + 0) * 64 + 4 * tj];
            float4 b1 = *(const float4*)&Bv[(cc4 + 1) * 64 + 4 * tj];
            float4 b2 = *(const float4*)&Bv[(cc4 + 2) * 64 + 4 * tj];
            float4 b3 = *(const float4*)&Bv[(cc4 + 3) * 64 + 4 * tj];
#pragma unroll
            for (int r = 0; r < 4; r++) {
                float4 ar = *(const float4*)&Av[(4 * ti + r) * 64 + cc4];
                mk44(ar, b0, b1, b2, b3, acc[r]);
            }
        }
#pragma unroll
        for (int r = 0; r < 4; r++)
#pragma unroll
            for (int s = 0; s < 4; s++)
                atomicAdd(&g_Wp[(4 * ti + r) * 64 + 4 * tj + s], acc[r][s]);
    }
}

// ---------------- K23: merged S->SQ/SK/norms -> attn -> M  (grid 16, 512 thr) ----------------
__device__ __forceinline__ void gemm_nn(const float* A, const float* B, int row0, int c0,
                                        float acc[2][4]) {
#pragma unroll
    for (int cc4 = 0; cc4 < 64; cc4 += 4) {
        float4 b0 = *(const float4*)&B[(cc4 + 0) * 64 + c0];
        float4 b1 = *(const float4*)&B[(cc4 + 1) * 64 + c0];
        float4 b2 = *(const float4*)&B[(cc4 + 2) * 64 + c0];
        float4 b3 = *(const float4*)&B[(cc4 + 3) * 64 + c0];
        float4 a0 = *(const float4*)&A[row0 * 64 + cc4];
        float4 a1 = *(const float4*)&A[(row0 + 1) * 64 + cc4];
        mk44(a0, b0, b1, b2, b3, acc[0]);
        mk44(a1, b0, b1, b2, b3, acc[1]);
    }
}

__device__ __forceinline__ void gemm_tn(const float* A, const float* B, int row0, int c0,
                                        float acc[2][4]) {
#pragma unroll 8
    for (int cc = 0; cc < 64; cc++) {
        float4 bv = *(const float4*)&B[cc * 64 + c0];
        float a0 = A[cc * 64 + row0];
        float a1 = A[cc * 64 + row0 + 1];
        acc[0][0] += a0 * bv.x; acc[0][1] += a0 * bv.y;
        acc[0][2] += a0 * bv.z; acc[0][3] += a0 * bv.w;
        acc[1][0] += a1 * bv.x; acc[1][1] += a1 * bv.y;
        acc[1][2] += a1 * bv.z; acc[1][3] += a1 * bv.w;
    }
}

__global__ void k23_attn(const float* __restrict__ Wq, const float* __restrict__ Wk,
                         const float* __restrict__ rescale, const float* __restrict__ Wproj,
                         const float* __restrict__ Wv) {
    extern __shared__ float sm[];
    float* sA = sm;
    float* sB = sm + 4096;
    float* sC = sm + 8192;
    float* sD = sm + 12288;
    float* n2 = sm + 16384;   // [0:64) nq^2, [64:128) nk^2
    float* nrm = sm + 16512;
    int blk = blockIdx.x, b = blk >> 3, h = blk & 7;
    int tid = threadIdx.x;
    int row0 = (tid >> 4) * 2;
    int c0 = (tid & 15) * 4;

    for (int u = tid; u < 4096; u += 512) {
        int cc = u >> 6, j = u & 63;
        sA[u] = g_S[b * 4096 + u];
        sB[u] = Wq[cc * HD + h * 64 + j];
        sC[u] = Wk[cc * HD + h * 64 + j];
    }
    if (tid < 128) n2[tid] = 0.f;
    __syncthreads();
    float resc = rescale[h];

    // GEMM1: sD = S @ Wq
    float acc1[2][4];
#pragma unroll
    for (int r = 0; r < 2; r++)
#pragma unroll
        for (int s = 0; s < 4; s++) acc1[r][s] = 0.f;
    gemm_nn(sA, sB, row0, c0, acc1);
#pragma unroll
    for (int r = 0; r < 2; r++)
        *(float4*)&sD[(row0 + r) * 64 + c0] =
            make_float4(acc1[r][0], acc1[r][1], acc1[r][2], acc1[r][3]);
    __syncthreads();

    // nq partial (Wq . SQ) + GEMM2 (SK) into regs
    {
        int j = tid & 63, cp = tid >> 6;
        float p = 0.f;
#pragma unroll
        for (int k = 0; k < 8; k++) {
            int c = cp * 8 + k;
            p += sB[c * 64 + j] * sD[c * 64 + j];
        }
        atomicAdd(&n2[j], p);
    }
    float acc2[2][4];
#pragma unroll
    for (int r = 0; r < 2; r++)
#pragma unroll
        for (int s = 0; s < 4; s++) acc2[r][s] = 0.f;
    gemm_nn(sA, sC, row0, c0, acc2);
    __syncthreads();
#pragma unroll
    for (int r = 0; r < 2; r++)
        *(float4*)&sB[(row0 + r) * 64 + c0] =
            make_float4(acc2[r][0], acc2[r][1], acc2[r][2], acc2[r][3]);   // sB = SK
    __syncthreads();

    // nk partial (Wk . SK)
    {
        int i = tid & 63, cp = tid >> 6;
        float p = 0.f;
#pragma unroll
        for (int k = 0; k < 8; k++) {
            int c = cp * 8 + k;
            p += sC[c * 64 + i] * sB[c * 64 + i];
        }
        atomicAdd(&n2[64 + i], p);
    }
    __syncthreads();
    if (tid < 128) nrm[tid] = fmaxf(sqrtf(fmaxf(n2[tid], 0.f)), 1e-12f);

    // GEMM3: G[i][j] = sum_c Wk[c][i] * SQ[c][j]; load Wproj into sB (SK dead)
    float acc3[2][4];
#pragma unroll
    for (int r = 0; r < 2; r++)
#pragma unroll
        for (int s = 0; s < 4; s++) acc3[r][s] = 0.f;
    gemm_tn(sC, sD, row0, c0, acc3);
    for (int u = tid; u < 4096; u += 512) sB[u] = Wproj[h * 4096 + u];
    __syncthreads();
#pragma unroll
    for (int r = 0; r < 2; r++) {
        float ri = resc / nrm[64 + row0 + r];
#pragma unroll
        for (int s = 0; s < 4; s++)
            sA[(row0 + r) * 64 + c0 + s] = acc3[r][s] * ri / nrm[c0 + s];
    }
    __syncthreads();

    // parallel softmax over rows of sA (8 threads/row)
    {
        int row = tid >> 3, g = tid & 7;
        float4 v0 = *(const float4*)&sA[row * 64 + g * 8];
        float4 v1 = *(const float4*)&sA[row * 64 + g * 8 + 4];
        float m = fmaxf(fmaxf(fmaxf(v0.x, v0.y), fmaxf(v0.z, v0.w)),
                        fmaxf(fmaxf(v1.x, v1.y), fmaxf(v1.z, v1.w)));
#pragma unroll
        for (int k = 1; k < 8; k <<= 1) m = fmaxf(m, __shfl_xor_sync(0xffffffffu, m, k, 8));
        v0.x = expf(v0.x - m); v0.y = expf(v0.y - m); v0.z = expf(v0.z - m); v0.w = expf(v0.w - m);
        v1.x = expf(v1.x - m); v1.y = expf(v1.y - m); v1.z = expf(v1.z - m); v1.w = expf(v1.w - m);
        float ssum = v0.x + v0.y + v0.z + v0.w + v1.x + v1.y + v1.z + v1.w;
#pragma unroll
        for (int k = 1; k < 8; k <<= 1) ssum += __shfl_xor_sync(0xffffffffu, ssum, k, 8);
        float inv = 1.f / ssum;
        v0.x *= inv; v0.y *= inv; v0.z *= inv; v0.w *= inv;
        v1.x *= inv; v1.y *= inv; v1.z *= inv; v1.w *= inv;
        *(float4*)&sA[row * 64 + g * 8] = v0;
        *(float4*)&sA[row * 64 + g * 8 + 4] = v1;
    }
    __syncthreads();

    // GEMM4: B[j][d] = sum_i attn[i][j] * Wproj[i][d] -> sD ; load Wv into sC
    float acc4[2][4];
#pragma unroll
    for (int r = 0; r < 2; r++)
#pragma unroll
        for (int s = 0; s < 4; s++) acc4[r][s] = 0.f;
    gemm_tn(sA, sB, row0, c0, acc4);
#pragma unroll
    for (int r = 0; r < 2; r++)
        *(float4*)&sD[(row0 + r) * 64 + c0] =
            make_float4(acc4[r][0], acc4[r][1], acc4[r][2], acc4[r][3]);
    for (int u = tid; u < 4096; u += 512) sC[u] = Wv[(u >> 6) * HD + h * 64 + (u & 63)];
    __syncthreads();

    // GEMM5: M[c][d] = sum_j Wv[c][j] * B[j][d] -> atomic g_M
    float acc5[2][4];
#pragma unroll
    for (int r = 0; r < 2; r++)
#pragma unroll
        for (int s = 0; s < 4; s++) acc5[r][s] = 0.f;
    gemm_nn(sC, sD, row0, c0, acc5);
#pragma unroll
    for (int r = 0; r < 2; r++)
#pragma unroll
        for (int s = 0; s < 4; s++)
            atomicAdd(&g_M[b * 4096 + (row0 + r) * 64 + c0 + s], acc5[r][s]);
}

// ---------------- K4a: p_pre = x @ Wp + bc1d -> g_P  (grid 1024, 512 thr, 128 pix/blk) ----------------
__global__ void k4a_P(const float* __restrict__ x, const float* __restrict__ bc1d) {
    extern __shared__ float sm[];
    float* Wps = sm;          // 4096
    float* xs = sm + 4096;    // 8192
    float* bc = sm + 12288;   // 64
    int tid = threadIdx.x;
    size_t base = (size_t)blockIdx.x * 8192;
    const float4* src = (const float4*)(x + base);
    for (int u = tid; u < 2048; u += 512) ((float4*)xs)[u] = src[u];
    for (int u = tid; u < 1024; u += 512) ((float4*)Wps)[u] = ((const float4*)g_Wp)[u];
    if (tid < 64) bc[tid] = bc1d[tid];
    __syncthreads();

    int ti = tid >> 4, tj = tid & 15;   // ti 0..31 -> 4 pixels; tj -> 4 channels
    float acc[4][4];
#pragma unroll
    for (int r = 0; r < 4; r++)
#pragma unroll
        for (int s = 0; s < 4; s++) acc[r][s] = 0.f;
#pragma unroll
    for (int cc4 = 0; cc4 < 64; cc4 += 4) {
        float4 b0 = *(const float4*)&Wps[(cc4 + 0) * 64 + 4 * tj];
        float4 b1 = *(const float4*)&Wps[(cc4 + 1) * 64 + 4 * tj];
        float4 b2 = *(const float4*)&Wps[(cc4 + 2) * 64 + 4 * tj];
        float4 b3 = *(const float4*)&Wps[(cc4 + 3) * 64 + 4 * tj];
#pragma unroll
        for (int r = 0; r < 4; r++) {
            float4 ar = *(const float4*)&xs[(4 * ti + r) * 64 + cc4];
            mk44(ar, b0, b1, b2, b3, acc[r]);
        }
    }
    float4 bcv = *(const float4*)&bc[4 * tj];
#pragma unroll
    for (int r = 0; r < 4; r++) {
        float4 o = make_float4(acc[r][0] + bcv.x, acc[r][1] + bcv.y,
                               acc[r][2] + bcv.z, acc[r][3] + bcv.w);
        *(float4*)&g_P[base + (size_t)(4 * ti + r) * 64 + 4 * tj] = o;
    }
}

// ---------------- K4b: conv1+GELU+conv2 + x@M + bproj -> out (grid 2048, 256 thr) ----------------
__device__ __forceinline__ float gelu_f(float a) {
    return 0.5f * a * (1.f + erff(a * 0.70710678118654752f));
}

__global__ void k4b_main(const float* __restrict__ x, const float* __restrict__ bproj,
                         const float* __restrict__ Wpe1, const float* __restrict__ Wpe2,
                         float* __restrict__ out) {
    extern __shared__ float sm4[];
    float* ps  = sm4;           // 12x12x64 = 9216
    float* p1  = ps + 9216;     // 10x10x64 = 6400
    float* xs  = p1 + 6400;     // 8x8x64   = 4096
    float* Ms  = xs + 4096;     // 4096
    float* w1t = Ms + 4096;     // 576  (transposed: [k][c])
    float* w2s = w1t + 576;     // 576  (original:   [c][k])
    float* bps = w2s + 576;     // 64
    int blk = blockIdx.x;
    int b = blk >> 10;
    int rem = blk & 1023;
    int y0 = (rem >> 5) * 8, x0 = (rem & 31) * 8;
    int tid = threadIdx.x;

    for (int u = tid; u < 1024; u += 256)
        ((float4*)Ms)[u] = ((const float4*)(g_M + b * 4096))[u];
    for (int u = tid; u < 576; u += 256) {
        int c = u / 9, k = u - c * 9;
        w1t[k * 64 + c] = Wpe1[u];
        w2s[u] = Wpe2[u];
    }
    if (tid < 64) bps[tid] = bproj[tid];
    for (int u = tid; u < 1024; u += 256) {
        int py = u >> 7, off = u & 127;
        const float4* src = (const float4*)(x + (((size_t)(b * HH + y0 + py)) * WW + x0) * 64);
        ((float4*)xs)[py * 128 + off] = src[off];
    }
    for (int u = tid; u < 2304; u += 256) {   // halo p_pre (float4)
        int pidx = u >> 4, cg = (u & 15) * 4;
        int py = pidx / 12, pxx = pidx - py * 12;
        int gy = y0 - 2 + py, gx = x0 - 2 + pxx;
        float4 v = make_float4(0.f, 0.f, 0.f, 0.f);
        if ((unsigned)gy < HH && (unsigned)gx < WW)
            v = *(const float4*)&g_P[(((size_t)(b * HH + gy)) * WW + gx) * 64 + cg];
        *(float4*)&ps[pidx * 64 + cg] = v;
    }
    __syncthreads();

    for (int u = tid; u < 1600; u += 256) {   // conv1 + GELU (float4 over channels)
        int pidx = u >> 4, cg = (u & 15) * 4;
        int py = pidx / 10, pxx = pidx - py * 10;
        int gy = y0 - 1 + py, gx = x0 - 1 + pxx;
        float4 a = make_float4(0.f, 0.f, 0.f, 0.f);
        if ((unsigned)gy < HH && (unsigned)gx < WW) {
#pragma unroll
            for (int ky = 0; ky < 3; ky++)
#pragma unroll
                for (int kx = 0; kx < 3; kx++) {
                    int k = ky * 3 + kx;
                    float4 pv = *(const float4*)&ps[((py + ky) * 12 + pxx + kx) * 64 + cg];
                    float4 wv = *(const float4*)&w1t[k * 64 + cg];
                    a.x += pv.x * wv.x; a.y += pv.y * wv.y;
                    a.z += pv.z * wv.z; a.w += pv.w * wv.w;
                }
            a.x = gelu_f(a.x); a.y = gelu_f(a.y); a.z = gelu_f(a.z); a.w = gelu_f(a.w);
        }
        *(float4*)&p1[pidx * 64 + cg] = a;
    }
    __syncthreads();

    int ti = tid >> 4, tj = tid & 15;
    float wr[4][9];
#pragma unroll
    for (int s = 0; s < 4; s++)
#pragma unroll
        for (int k = 0; k < 9; k++) wr[s][k] = w2s[(4 * tj + s) * 9 + k];

    float acc[4][4];
#pragma unroll
    for (int r = 0; r < 4; r++)
#pragma unroll
        for (int s = 0; s < 4; s++) acc[r][s] = 0.f;
#pragma unroll
    for (int cc4 = 0; cc4 < 64; cc4 += 4) {   // x @ M (vectorized)
        float4 b0 = *(const float4*)&Ms[(cc4 + 0) * 64 + 4 * tj];
        float4 b1 = *(const float4*)&Ms[(cc4 + 1) * 64 + 4 * tj];
        float4 b2 = *(const float4*)&Ms[(cc4 + 2) * 64 + 4 * tj];
        float4 b3 = *(const float4*)&Ms[(cc4 + 3) * 64 + 4 * tj];
#pragma unroll
        for (int r = 0; r < 4; r++) {
            float4 ar = *(const float4*)&xs[(4 * ti + r) * 64 + cc4];
            mk44(ar, b0, b1, b2, b3, acc[r]);
        }
    }
#pragma unroll
    for (int r = 0; r < 4; r++) {             // conv2 + combine + store
        int pl = 4 * ti + r, py = pl >> 3, pxx = pl & 7;
        float cv[4] = {0.f, 0.f, 0.f, 0.f};
#pragma unroll
        for (int ky = 0; ky < 3; ky++)
#pragma unroll
            for (int kx = 0; kx < 3; kx++) {
                int k = ky * 3 + kx;
                float4 pv = *(const float4*)&p1[((py + ky) * 10 + pxx + kx) * 64 + 4 * tj];
                cv[0] += pv.x * wr[0][k];
                cv[1] += pv.y * wr[1][k];
                cv[2] += pv.z * wr[2][k];
                cv[3] += pv.w * wr[3][k];
            }
        float4 o;
        o.x = acc[r][0] + cv[0] + bps[4 * tj + 0];
        o.y = acc[r][1] + cv[1] + bps[4 * tj + 1];
        o.z = acc[r][2] + cv[2] + bps[4 * tj + 2];
        o.w = acc[r][3] + cv[3] + bps[4 * tj + 3];
        *(float4*)(out + (((size_t)(b * HH + y0 + py)) * WW + x0 + pxx) * 64 + 4 * tj) = o;
    }
}

// ---------------- launch ----------------
extern "C" void kernel_launch(void* const* d_in, const int* in_sizes, int n_in,
                              void* d_out, int out_size) {
    const float* x     = (const float*)d_in[0];
    const float* Wq    = (const float*)d_in[1];
    const float* Wk    = (const float*)d_in[2];
    const float* Wv    = (const float*)d_in[3];
    const float* resc  = (const float*)d_in[4];
    const float* Wproj = (const float*)d_in[5];
    const float* bproj = (const float*)d_in[6];
    const float* Wc1d  = (const float*)d_in[7];
    const float* bc1d  = (const float*)d_in[8];
    const float* Wpe1  = (const float*)d_in[9];
    const float* Wpe2  = (const float*)d_in[10];
    float* out = (float*)d_out;

    cudaFuncSetAttribute(k23_attn, cudaFuncAttributeMaxDynamicSharedMemorySize, 16640 * 4);
    cudaFuncSetAttribute(k4a_P, cudaFuncAttributeMaxDynamicSharedMemorySize, 12352 * 4);
    cudaFuncSetAttribute(k4b_main, cudaFuncAttributeMaxDynamicSharedMemorySize, 25024 * 4);

    k0_zero<<<8, 1024>>>();
    k1_S_Wp<<<136, 256>>>(x, Wv, Wc1d);
    k23_attn<<<16, 512, 16640 * 4>>>(Wq, Wk, resc, Wproj, Wv);
    k4a_P<<<1024, 512, 12352 * 4>>>(x, bc1d);
    k4b_main<<<2048, 256, 25024 * 4>>>(x, bproj, Wpe1, Wpe2, out);
}

// round 13
// speedup vs baseline: 1.4961x; 1.0034x over previous
#include <cuda_runtime.h>
#include <math.h>

#define HH 256
#define WW 256
#define HD 512

// ---------------- scratch (device globals) ----------------
__device__ float g_S[2 * 4096];                      // xd^T xd per batch
__device__ float g_M[2 * 4096];                      // Wv @ A^T @ Wproj per batch
__device__ float g_Wp[4096];                         // Wv @ Wc1d
__device__ float g_P[(size_t)2 * HH * WW * 64];      // p_pre

// 4x4 outer-product micro-op: acc[s] += sum_k a.k * bk.s
__device__ __forceinline__ void mk44(float4 a, float4 b0, float4 b1, float4 b2, float4 b3,
                                     float* acc) {
    acc[0] += a.x * b0.x + a.y * b1.x + a.z * b2.x + a.w * b3.x;
    acc[1] += a.x * b0.y + a.y * b1.y + a.z * b2.y + a.w * b3.y;
    acc[2] += a.x * b0.z + a.y * b1.z + a.z * b2.z + a.w * b3.z;
    acc[3] += a.x * b0.w + a.y * b1.w + a.z * b2.w + a.w * b3.w;
}

// ---------------- K0: zero accumulators ----------------
__global__ void k0_zero() {
    int i = blockIdx.x * 1024 + threadIdx.x;
    if (i < 8192) { g_S[i] = 0.f; g_M[i] = 0.f; }
    if (i < 4096) g_Wp[i] = 0.f;
}

// ---------------- K1: S partials (grid 128) ----------------
__global__ void k1_S(const float* __restrict__ x) {
    __shared__ float xs[16 * 64];
    int blk = blockIdx.x, tid = threadIdx.x;
    int b = blk >> 6, rp = blk & 63;      // 2 ds-rows per block
    int ti = tid >> 4, tj = tid & 15;
    int c4 = (tid & 15) * 4;              // channel group for loading
    int tl = tid >> 4;                    // token lane for loading
    float acc[4][4];
#pragma unroll
    for (int r = 0; r < 4; r++)
#pragma unroll
        for (int s = 0; s < 4; s++) acc[r][s] = 0.f;

    for (int g = 0; g < 16; g++) {
        int dr = rp * 2 + (g >> 3);
        int dc = (g & 7) * 16 + tl;
        int gy = dr * 2, gx = dc * 2;
        const float* p0 = x + (((size_t)b * HH + gy) * WW + gx) * 64 + c4;
        float4 v0 = *(const float4*)p0;
        float4 v1 = *(const float4*)(p0 + 64);
        float4 v2 = *(const float4*)(p0 + WW * 64);
        float4 v3 = *(const float4*)(p0 + WW * 64 + 64);
        float4 s4;
        s4.x = 0.25f * (v0.x + v1.x + v2.x + v3.x);
        s4.y = 0.25f * (v0.y + v1.y + v2.y + v3.y);
        s4.z = 0.25f * (v0.z + v1.z + v2.z + v3.z);
        s4.w = 0.25f * (v0.w + v1.w + v2.w + v3.w);
        *(float4*)&xs[tl * 64 + c4] = s4;
        __syncthreads();
#pragma unroll
        for (int t = 0; t < 16; t++) {
            float4 av = *(const float4*)&xs[t * 64 + 4 * ti];
            float4 bv = *(const float4*)&xs[t * 64 + 4 * tj];
            float a4[4] = {av.x, av.y, av.z, av.w};
            float b4[4] = {bv.x, bv.y, bv.z, bv.w};
#pragma unroll
            for (int r = 0; r < 4; r++)
#pragma unroll
                for (int s = 0; s < 4; s++) acc[r][s] += a4[r] * b4[s];
        }
        __syncthreads();
    }
    float* Sb = g_S + b * 4096;
#pragma unroll
    for (int r = 0; r < 4; r++)
#pragma unroll
        for (int s = 0; s < 4; s++)
            atomicAdd(&Sb[(4 * ti + r) * 64 + 4 * tj + s], acc[r][s]);
}

// ---------------- KWp: Wp = Wv @ Wc1d partials (grid 8) ----------------
__global__ void kWp(const float* __restrict__ Wv, const float* __restrict__ Wc1d) {
    __shared__ float sm[8192];
    float* Av = sm;            // Wv[c][ff]
    float* Bv = sm + 4096;     // Wc1d[ff][d]
    int tid = threadIdx.x;
    int f0 = blockIdx.x * 64;
    for (int u = tid; u < 4096; u += 256) {
        Av[u] = Wv[(u >> 6) * HD + f0 + (u & 63)];
        Bv[u] = Wc1d[f0 * 64 + u];
    }
    __syncthreads();
    int ti = tid >> 4, tj = tid & 15;
    float acc[4][4];
#pragma unroll
    for (int r = 0; r < 4; r++)
#pragma unroll
        for (int s = 0; s < 4; s++) acc[r][s] = 0.f;
#pragma unroll
    for (int cc4 = 0; cc4 < 64; cc4 += 4) {
        float4 b0 = *(const float4*)&Bv[(cc4 + 0) * 64 + 4 * tj];
        float4 b1 = *(const float4*)&Bv[(cc4 + 1) * 64 + 4 * tj];
        float4 b2 = *(const float4*)&Bv[(cc4 + 2) * 64 + 4 * tj];
        float4 b3 = *(const float4*)&Bv[(cc4 + 3) * 64 + 4 * tj];
#pragma unroll
        for (int r = 0; r < 4; r++) {
            float4 ar = *(const float4*)&Av[(4 * ti + r) * 64 + cc4];
            mk44(ar, b0, b1, b2, b3, acc[r]);
        }
    }
#pragma unroll
    for (int r = 0; r < 4; r++)
#pragma unroll
        for (int s = 0; s < 4; s++)
            atomicAdd(&g_Wp[(4 * ti + r) * 64 + 4 * tj + s], acc[r][s]);
}

// ---------------- K23: merged S->SQ/SK/norms -> attn -> M  (grid 16, 512 thr) ----------------
__device__ __forceinline__ void gemm_nn(const float* A, const float* B, int row0, int c0,
                                        float acc[2][4]) {
#pragma unroll
    for (int cc4 = 0; cc4 < 64; cc4 += 4) {
        float4 b0 = *(const float4*)&B[(cc4 + 0) * 64 + c0];
        float4 b1 = *(const float4*)&B[(cc4 + 1) * 64 + c0];
        float4 b2 = *(const float4*)&B[(cc4 + 2) * 64 + c0];
        float4 b3 = *(const float4*)&B[(cc4 + 3) * 64 + c0];
        float4 a0 = *(const float4*)&A[row0 * 64 + cc4];
        float4 a1 = *(const float4*)&A[(row0 + 1) * 64 + cc4];
        mk44(a0, b0, b1, b2, b3, acc[0]);
        mk44(a1, b0, b1, b2, b3, acc[1]);
    }
}

__device__ __forceinline__ void gemm_tn(const float* A, const float* B, int row0, int c0,
                                        float acc[2][4]) {
#pragma unroll 8
    for (int cc = 0; cc < 64; cc++) {
        float4 bv = *(const float4*)&B[cc * 64 + c0];
        float a0 = A[cc * 64 + row0];
        float a1 = A[cc * 64 + row0 + 1];
        acc[0][0] += a0 * bv.x; acc[0][1] += a0 * bv.y;
        acc[0][2] += a0 * bv.z; acc[0][3] += a0 * bv.w;
        acc[1][0] += a1 * bv.x; acc[1][1] += a1 * bv.y;
        acc[1][2] += a1 * bv.z; acc[1][3] += a1 * bv.w;
    }
}

__global__ void k23_attn(const float* __restrict__ Wq, const float* __restrict__ Wk,
                         const float* __restrict__ rescale, const float* __restrict__ Wproj,
                         const float* __restrict__ Wv) {
    extern __shared__ float sm[];
    float* sA = sm;
    float* sB = sm + 4096;
    float* sC = sm + 8192;
    float* sD = sm + 12288;
    float* n2 = sm + 16384;   // [0:64) nq^2, [64:128) nk^2
    float* nrm = sm + 16512;
    int blk = blockIdx.x, b = blk >> 3, h = blk & 7;
    int tid = threadIdx.x;
    int row0 = (tid >> 4) * 2;
    int c0 = (tid & 15) * 4;

    for (int u = tid; u < 4096; u += 512) {
        int cc = u >> 6, j = u & 63;
        sA[u] = g_S[b * 4096 + u];
        sB[u] = Wq[cc * HD + h * 64 + j];
        sC[u] = Wk[cc * HD + h * 64 + j];
    }
    if (tid < 128) n2[tid] = 0.f;
    __syncthreads();
    float resc = rescale[h];

    // GEMM1: sD = S @ Wq
    float acc1[2][4];
#pragma unroll
    for (int r = 0; r < 2; r++)
#pragma unroll
        for (int s = 0; s < 4; s++) acc1[r][s] = 0.f;
    gemm_nn(sA, sB, row0, c0, acc1);
#pragma unroll
    for (int r = 0; r < 2; r++)
        *(float4*)&sD[(row0 + r) * 64 + c0] =
            make_float4(acc1[r][0], acc1[r][1], acc1[r][2], acc1[r][3]);
    __syncthreads();

    // nq partial (Wq . SQ) + GEMM2 (SK) into regs
    {
        int j = tid & 63, cp = tid >> 6;
        float p = 0.f;
#pragma unroll
        for (int k = 0; k < 8; k++) {
            int c = cp * 8 + k;
            p += sB[c * 64 + j] * sD[c * 64 + j];
        }
        atomicAdd(&n2[j], p);
    }
    float acc2[2][4];
#pragma unroll
    for (int r = 0; r < 2; r++)
#pragma unroll
        for (int s = 0; s < 4; s++) acc2[r][s] = 0.f;
    gemm_nn(sA, sC, row0, c0, acc2);
    __syncthreads();
#pragma unroll
    for (int r = 0; r < 2; r++)
        *(float4*)&sB[(row0 + r) * 64 + c0] =
            make_float4(acc2[r][0], acc2[r][1], acc2[r][2], acc2[r][3]);   // sB = SK
    __syncthreads();

    // nk partial (Wk . SK)
    {
        int i = tid & 63, cp = tid >> 6;
        float p = 0.f;
#pragma unroll
        for (int k = 0; k < 8; k++) {
            int c = cp * 8 + k;
            p += sC[c * 64 + i] * sB[c * 64 + i];
        }
        atomicAdd(&n2[64 + i], p);
    }
    __syncthreads();
    if (tid < 128) nrm[tid] = fmaxf(sqrtf(fmaxf(n2[tid], 0.f)), 1e-12f);

    // GEMM3: G[i][j] = sum_c Wk[c][i] * SQ[c][j]; load Wproj into sB (SK dead)
    float acc3[2][4];
#pragma unroll
    for (int r = 0; r < 2; r++)
#pragma unroll
        for (int s = 0; s < 4; s++) acc3[r][s] = 0.f;
    gemm_tn(sC, sD, row0, c0, acc3);
    for (int u = tid; u < 4096; u += 512) sB[u] = Wproj[h * 4096 + u];
    __syncthreads();
#pragma unroll
    for (int r = 0; r < 2; r++) {
        float ri = resc / nrm[64 + row0 + r];
#pragma unroll
        for (int s = 0; s < 4; s++)
            sA[(row0 + r) * 64 + c0 + s] = acc3[r][s] * ri / nrm[c0 + s];
    }
    __syncthreads();

    // parallel softmax over rows of sA (8 threads/row)
    {
        int row = tid >> 3, g = tid & 7;
        float4 v0 = *(const float4*)&sA[row * 64 + g * 8];
        float4 v1 = *(const float4*)&sA[row * 64 + g * 8 + 4];
        float m = fmaxf(fmaxf(fmaxf(v0.x, v0.y), fmaxf(v0.z, v0.w)),
                        fmaxf(fmaxf(v1.x, v1.y), fmaxf(v1.z, v1.w)));
#pragma unroll
        for (int k = 1; k < 8; k <<= 1) m = fmaxf(m, __shfl_xor_sync(0xffffffffu, m, k, 8));
        v0.x = expf(v0.x - m); v0.y = expf(v0.y - m); v0.z = expf(v0.z - m); v0.w = expf(v0.w - m);
        v1.x = expf(v1.x - m); v1.y = expf(v1.y - m); v1.z = expf(v1.z - m); v1.w = expf(v1.w - m);
        float ssum = v0.x + v0.y + v0.z + v0.w + v1.x + v1.y + v1.z + v1.w;
#pragma unroll
        for (int k = 1; k < 8; k <<= 1) ssum += __shfl_xor_sync(0xffffffffu, ssum, k, 8);
        float inv = 1.f / ssum;
        v0.x *= inv; v0.y *= inv; v0.z *= inv; v0.w *= inv;
        v1.x *= inv; v1.y *= inv; v1.z *= inv; v1.w *= inv;
        *(float4*)&sA[row * 64 + g * 8] = v0;
        *(float4*)&sA[row * 64 + g * 8 + 4] = v1;
    }
    __syncthreads();

    // GEMM4: B[j][d] = sum_i attn[i][j] * Wproj[i][d] -> sD ; load Wv into sC
    float acc4[2][4];
#pragma unroll
    for (int r = 0; r < 2; r++)
#pragma unroll
        for (int s = 0; s < 4; s++) acc4[r][s] = 0.f;
    gemm_tn(sA, sB, row0, c0, acc4);
#pragma unroll
    for (int r = 0; r < 2; r++)
        *(float4*)&sD[(row0 + r) * 64 + c0] =
            make_float4(acc4[r][0], acc4[r][1], acc4[r][2], acc4[r][3]);
    for (int u = tid; u < 4096; u += 512) sC[u] = Wv[(u >> 6) * HD + h * 64 + (u & 63)];
    __syncthreads();

    // GEMM5: M[c][d] = sum_j Wv[c][j] * B[j][d] -> atomic g_M
    float acc5[2][4];
#pragma unroll
    for (int r = 0; r < 2; r++)
#pragma unroll
        for (int s = 0; s < 4; s++) acc5[r][s] = 0.f;
    gemm_nn(sC, sD, row0, c0, acc5);
#pragma unroll
    for (int r = 0; r < 2; r++)
#pragma unroll
        for (int s = 0; s < 4; s++)
            atomicAdd(&g_M[b * 4096 + (row0 + r) * 64 + c0 + s], acc5[r][s]);
}

// ---------------- K4a: p_pre = x @ Wp + bc1d -> g_P ----------------
// grid 1024, 256 thr, 128 px/block; 4px x 8ch register blocking; xs rows padded to 68
#define XSP 68
__global__ void k4a_P(const float* __restrict__ x, const float* __restrict__ bc1d) {
    extern __shared__ float sm[];
    float* Wps = sm;            // 4096
    float* xs  = sm + 4096;     // 128*68 = 8704
    float* bc  = sm + 12800;    // 64
    int tid = threadIdx.x;
    size_t base = (size_t)blockIdx.x * 8192;
    const float4* src = (const float4*)(x + base);
    for (int u = tid; u < 2048; u += 256) {
        int p = u >> 4, c4 = (u & 15) * 4;
        *(float4*)&xs[p * XSP + c4] = src[u];
    }
    for (int u = tid; u < 1024; u += 256) ((float4*)Wps)[u] = ((const float4*)g_Wp)[u];
    if (tid < 64) bc[tid] = bc1d[tid];
    __syncthreads();

    int pg = tid >> 3;          // 0..31 -> pixels 4pg..4pg+3
    int cg = (tid & 7) * 8;     // 8 channels
    float acc[4][8];
#pragma unroll
    for (int r = 0; r < 4; r++)
#pragma unroll
        for (int s = 0; s < 8; s++) acc[r][s] = 0.f;
#pragma unroll
    for (int cc4 = 0; cc4 < 64; cc4 += 4) {
        float4 bA[4], bB[4];
#pragma unroll
        for (int c = 0; c < 4; c++) {
            bA[c] = *(const float4*)&Wps[(cc4 + c) * 64 + cg];
            bB[c] = *(const float4*)&Wps[(cc4 + c) * 64 + cg + 4];
        }
#pragma unroll
        for (int r = 0; r < 4; r++) {
            float4 a = *(const float4*)&xs[(4 * pg + r) * XSP + cc4];
            mk44(a, bA[0], bA[1], bA[2], bA[3], &acc[r][0]);
            mk44(a, bB[0], bB[1], bB[2], bB[3], &acc[r][4]);
        }
    }
    float4 bc0 = *(const float4*)&bc[cg];
    float4 bc1 = *(const float4*)&bc[cg + 4];
#pragma unroll
    for (int r = 0; r < 4; r++) {
        int p = 4 * pg + r;
        float4 o0 = make_float4(acc[r][0] + bc0.x, acc[r][1] + bc0.y,
                                acc[r][2] + bc0.z, acc[r][3] + bc0.w);
        float4 o1 = make_float4(acc[r][4] + bc1.x, acc[r][5] + bc1.y,
                                acc[r][6] + bc1.z, acc[r][7] + bc1.w);
        *(float4*)&g_P[base + (size_t)p * 64 + cg] = o0;
        *(float4*)&g_P[base + (size_t)p * 64 + cg + 4] = o1;
    }
}

// ---------------- K4b: conv1+GELU+conv2 + x@M + bproj -> out (grid 2048, 256 thr) ----------------
__device__ __forceinline__ float gelu_f(float a) {
    return 0.5f * a * (1.f + erff(a * 0.70710678118654752f));
}

__global__ void k4b_main(const float* __restrict__ x, const float* __restrict__ bproj,
                         const float* __restrict__ Wpe1, const float* __restrict__ Wpe2,
                         float* __restrict__ out) {
    extern __shared__ float sm4[];
    float* ps  = sm4;           // 12x12x64 = 9216
    float* p1  = ps + 9216;     // 10x10x64 = 6400
    float* xs  = p1 + 6400;     // 8x8x64   = 4096
    float* Ms  = xs + 4096;     // 4096
    float* w1t = Ms + 4096;     // 576  (transposed: [k][c])
    float* w2s = w1t + 576;     // 576  (original:   [c][k])
    float* bps = w2s + 576;     // 64
    int blk = blockIdx.x;
    int b = blk >> 10;
    int rem = blk & 1023;
    int y0 = (rem >> 5) * 8, x0 = (rem & 31) * 8;
    int tid = threadIdx.x;

    for (int u = tid; u < 1024; u += 256)
        ((float4*)Ms)[u] = ((const float4*)(g_M + b * 4096))[u];
    for (int u = tid; u < 576; u += 256) {
        int c = u / 9, k = u - c * 9;
        w1t[k * 64 + c] = Wpe1[u];
        w2s[u] = Wpe2[u];
    }
    if (tid < 64) bps[tid] = bproj[tid];
    for (int u = tid; u < 1024; u += 256) {
        int py = u >> 7, off = u & 127;
        const float4* src = (const float4*)(x + (((size_t)(b * HH + y0 + py)) * WW + x0) * 64);
        ((float4*)xs)[py * 128 + off] = src[off];
    }
    for (int u = tid; u < 2304; u += 256) {   // halo p_pre (float4)
        int pidx = u >> 4, cgh = (u & 15) * 4;
        int py = pidx / 12, pxx = pidx - py * 12;
        int gy = y0 - 2 + py, gx = x0 - 2 + pxx;
        float4 v = make_float4(0.f, 0.f, 0.f, 0.f);
        if ((unsigned)gy < HH && (unsigned)gx < WW)
            v = *(const float4*)&g_P[(((size_t)(b * HH + gy)) * WW + gx) * 64 + cgh];
        *(float4*)&ps[pidx * 64 + cgh] = v;
    }
    __syncthreads();

    // conv1 + GELU: each thread has a FIXED channel group -> hoist weights to regs
    {
        int cgc = (tid & 15) * 4;
        float4 wv1[9];
#pragma unroll
        for (int k = 0; k < 9; k++) wv1[k] = *(const float4*)&w1t[k * 64 + cgc];
        for (int u = tid; u < 1600; u += 256) {
            int pidx = u >> 4;
            int py = pidx / 10, pxx = pidx - py * 10;
            int gy = y0 - 1 + py, gx = x0 - 1 + pxx;
            float4 a = make_float4(0.f, 0.f, 0.f, 0.f);
            if ((unsigned)gy < HH && (unsigned)gx < WW) {
#pragma unroll
                for (int ky = 0; ky < 3; ky++)
#pragma unroll
                    for (int kx = 0; kx < 3; kx++) {
                        int k = ky * 3 + kx;
                        float4 pv = *(const float4*)&ps[((py + ky) * 12 + pxx + kx) * 64 + cgc];
                        a.x += pv.x * wv1[k].x; a.y += pv.y * wv1[k].y;
                        a.z += pv.z * wv1[k].z; a.w += pv.w * wv1[k].w;
                    }
                a.x = gelu_f(a.x); a.y = gelu_f(a.y); a.z = gelu_f(a.z); a.w = gelu_f(a.w);
            }
            *(float4*)&p1[pidx * 64 + cgc] = a;
        }
    }
    __syncthreads();

    int ti = tid >> 4, tj = tid & 15;
    float wr[4][9];
#pragma unroll
    for (int s = 0; s < 4; s++)
#pragma unroll
        for (int k = 0; k < 9; k++) wr[s][k] = w2s[(4 * tj + s) * 9 + k];

    float acc[4][4];
#pragma unroll
    for (int r = 0; r < 4; r++)
#pragma unroll
        for (int s = 0; s < 4; s++) acc[r][s] = 0.f;
#pragma unroll
    for (int cc4 = 0; cc4 < 64; cc4 += 4) {   // x @ M (vectorized)
        float4 b0 = *(const float4*)&Ms[(cc4 + 0) * 64 + 4 * tj];
        float4 b1 = *(const float4*)&Ms[(cc4 + 1) * 64 + 4 * tj];
        float4 b2 = *(const float4*)&Ms[(cc4 + 2) * 64 + 4 * tj];
        float4 b3 = *(const float4*)&Ms[(cc4 + 3) * 64 + 4 * tj];
#pragma unroll
        for (int r = 0; r < 4; r++) {
            float4 ar = *(const float4*)&xs[(4 * ti + r) * 64 + cc4];
            mk44(ar, b0, b1, b2, b3, acc[r]);
        }
    }
#pragma unroll
    for (int r = 0; r < 4; r++) {             // conv2 + combine + store
        int pl = 4 * ti + r, py = pl >> 3, pxx = pl & 7;
        float cv[4] = {0.f, 0.f, 0.f, 0.f};
#pragma unroll
        for (int ky = 0; ky < 3; ky++)
#pragma unroll
            for (int kx = 0; kx < 3; kx++) {
                int k = ky * 3 + kx;
                float4 pv = *(const float4*)&p1[((py + ky) * 10 + pxx + kx) * 64 + 4 * tj];
                cv[0] += pv.x * wr[0][k];
                cv[1] += pv.y * wr[1][k];
                cv[2] += pv.z * wr[2][k];
                cv[3] += pv.w * wr[3][k];
            }
        float4 o;
        o.x = acc[r][0] + cv[0] + bps[4 * tj + 0];
        o.y = acc[r][1] + cv[1] + bps[4 * tj + 1];
        o.z = acc[r][2] + cv[2] + bps[4 * tj + 2];
        o.w = acc[r][3] + cv[3] + bps[4 * tj + 3];
        *(float4*)(out + (((size_t)(b * HH + y0 + py)) * WW + x0 + pxx) * 64 + 4 * tj) = o;
    }
}

// ---------------- launch ----------------
extern "C" void kernel_launch(void* const* d_in, const int* in_sizes, int n_in,
                              void* d_out, int out_size) {
    const float* x     = (const float*)d_in[0];
    const float* Wq    = (const float*)d_in[1];
    const float* Wk    = (const float*)d_in[2];
    const float* Wv    = (const float*)d_in[3];
    const float* resc  = (const float*)d_in[4];
    const float* Wproj = (const float*)d_in[5];
    const float* bproj = (const float*)d_in[6];
    const float* Wc1d  = (const float*)d_in[7];
    const float* bc1d  = (const float*)d_in[8];
    const float* Wpe1  = (const float*)d_in[9];
    const float* Wpe2  = (const float*)d_in[10];
    float* out = (float*)d_out;

    // one-time infra (created on the first, non-captured correctness call)
    static cudaStream_t s_aux = [] {
        cudaStream_t s; cudaStreamCreateWithFlags(&s, cudaStreamNonBlocking); return s;
    }();
    static cudaEvent_t ev_fork = [] {
        cudaEvent_t e; cudaEventCreateWithFlags(&e, cudaEventDisableTiming); return e;
    }();
    static cudaEvent_t ev_join = [] {
        cudaEvent_t e; cudaEventCreateWithFlags(&e, cudaEventDisableTiming); return e;
    }();

    cudaFuncSetAttribute(k23_attn, cudaFuncAttributeMaxDynamicSharedMemorySize, 16640 * 4);
    cudaFuncSetAttribute(k4a_P, cudaFuncAttributeMaxDynamicSharedMemorySize, 12864 * 4);
    cudaFuncSetAttribute(k4b_main, cudaFuncAttributeMaxDynamicSharedMemorySize, 25024 * 4);

    k0_zero<<<8, 1024>>>();
    cudaEventRecord(ev_fork, 0);
    cudaStreamWaitEvent(s_aux, ev_fork, 0);

    // aux branch: S gram + attention -> g_M
    k1_S<<<128, 256, 0, s_aux>>>(x);
    k23_attn<<<16, 512, 16640 * 4, s_aux>>>(Wq, Wk, resc, Wproj, Wv);
    cudaEventRecord(ev_join, s_aux);

    // main branch: Wp + big P GEMM
    kWp<<<8, 256>>>(Wv, Wc1d);
    k4a_P<<<1024, 256, 12864 * 4>>>(x, bc1d);

    cudaStreamWaitEvent(0, ev_join, 0);
    k4b_main<<<2048, 256, 25024 * 4>>>(x, bproj, Wpe1, Wpe2, out);
}

// round 14
// speedup vs baseline: 1.5492x; 1.0355x over previous
#include <cuda_runtime.h>
#include <math.h>

#define HH 256
#define WW 256
#define HD 512

// ---------------- scratch (device globals) ----------------
__device__ float g_S[2 * 4096];                      // xd^T xd per batch
__device__ float g_M[2 * 4096];                      // Wv @ A^T @ Wproj per batch
__device__ float g_Wp[4096];                         // Wv @ Wc1d
__device__ float g_P[(size_t)2 * HH * WW * 64];      // p_pre

// 4x4 outer-product micro-op: acc[s] += sum_k a.k * bk.s
__device__ __forceinline__ void mk44(float4 a, float4 b0, float4 b1, float4 b2, float4 b3,
                                     float* acc) {
    acc[0] += a.x * b0.x + a.y * b1.x + a.z * b2.x + a.w * b3.x;
    acc[1] += a.x * b0.y + a.y * b1.y + a.z * b2.y + a.w * b3.y;
    acc[2] += a.x * b0.z + a.y * b1.z + a.z * b2.z + a.w * b3.z;
    acc[3] += a.x * b0.w + a.y * b1.w + a.z * b2.w + a.w * b3.w;
}

// ---------------- K0: zero accumulators (g_S, g_M only) ----------------
__global__ void k0_zero() {
    int i = blockIdx.x * 1024 + threadIdx.x;
    if (i < 8192) { g_S[i] = 0.f; g_M[i] = 0.f; }
}

// ---------------- KWp: Wp = Wv @ Wc1d, direct (grid 16, no atomics) ----------------
__global__ void kWp(const float* __restrict__ Wv, const float* __restrict__ Wc1d) {
    __shared__ float Wc[4096];    // Wc1d chunk [64f][64d]
    __shared__ float Wvs[256];    // Wv chunk [4c][64f]
    int tid = threadIdx.x;
    int c0 = blockIdx.x * 4;
    int c = tid >> 6, d = tid & 63;
    float acc = 0.f;
    for (int f0 = 0; f0 < HD; f0 += 64) {
        __syncthreads();
        for (int u = tid; u < 1024; u += 256)
            ((float4*)Wc)[u] = ((const float4*)(Wc1d + f0 * 64))[u];
        {
            int cc = tid >> 6, f = tid & 63;
            Wvs[tid] = Wv[(c0 + cc) * HD + f0 + f];
        }
        __syncthreads();
#pragma unroll 16
        for (int f = 0; f < 64; f++)
            acc += Wvs[c * 64 + f] * Wc[f * 64 + d];
    }
    g_Wp[(c0 + c) * 64 + d] = acc;
}

// ---------------- K1: S partials (grid 128) ----------------
__global__ void k1_S(const float* __restrict__ x) {
    __shared__ float xs[16 * 64];
    int blk = blockIdx.x, tid = threadIdx.x;
    int b = blk >> 6, rp = blk & 63;      // 2 ds-rows per block
    int ti = tid >> 4, tj = tid & 15;
    int c4 = (tid & 15) * 4;              // channel group for loading
    int tl = tid >> 4;                    // token lane for loading
    float acc[4][4];
#pragma unroll
    for (int r = 0; r < 4; r++)
#pragma unroll
        for (int s = 0; s < 4; s++) acc[r][s] = 0.f;

    for (int g = 0; g < 16; g++) {
        int dr = rp * 2 + (g >> 3);
        int dc = (g & 7) * 16 + tl;
        int gy = dr * 2, gx = dc * 2;
        const float* p0 = x + (((size_t)b * HH + gy) * WW + gx) * 64 + c4;
        float4 v0 = *(const float4*)p0;
        float4 v1 = *(const float4*)(p0 + 64);
        float4 v2 = *(const float4*)(p0 + WW * 64);
        float4 v3 = *(const float4*)(p0 + WW * 64 + 64);
        float4 s4;
        s4.x = 0.25f * (v0.x + v1.x + v2.x + v3.x);
        s4.y = 0.25f * (v0.y + v1.y + v2.y + v3.y);
        s4.z = 0.25f * (v0.z + v1.z + v2.z + v3.z);
        s4.w = 0.25f * (v0.w + v1.w + v2.w + v3.w);
        *(float4*)&xs[tl * 64 + c4] = s4;
        __syncthreads();
#pragma unroll
        for (int t = 0; t < 16; t++) {
            float4 av = *(const float4*)&xs[t * 64 + 4 * ti];
            float4 bv = *(const float4*)&xs[t * 64 + 4 * tj];
            float a4[4] = {av.x, av.y, av.z, av.w};
            float b4[4] = {bv.x, bv.y, bv.z, bv.w};
#pragma unroll
            for (int r = 0; r < 4; r++)
#pragma unroll
                for (int s = 0; s < 4; s++) acc[r][s] += a4[r] * b4[s];
        }
        __syncthreads();
    }
    float* Sb = g_S + b * 4096;
#pragma unroll
    for (int r = 0; r < 4; r++)
#pragma unroll
        for (int s = 0; s < 4; s++)
            atomicAdd(&Sb[(4 * ti + r) * 64 + 4 * tj + s], acc[r][s]);
}

// ---------------- K23: merged S->SQ/SK/norms -> attn -> M  (grid 16, 512 thr) ----------------
__device__ __forceinline__ void gemm_nn(const float* A, const float* B, int row0, int c0,
                                        float acc[2][4]) {
#pragma unroll
    for (int cc4 = 0; cc4 < 64; cc4 += 4) {
        float4 b0 = *(const float4*)&B[(cc4 + 0) * 64 + c0];
        float4 b1 = *(const float4*)&B[(cc4 + 1) * 64 + c0];
        float4 b2 = *(const float4*)&B[(cc4 + 2) * 64 + c0];
        float4 b3 = *(const float4*)&B[(cc4 + 3) * 64 + c0];
        float4 a0 = *(const float4*)&A[row0 * 64 + cc4];
        float4 a1 = *(const float4*)&A[(row0 + 1) * 64 + cc4];
        mk44(a0, b0, b1, b2, b3, acc[0]);
        mk44(a1, b0, b1, b2, b3, acc[1]);
    }
}

__device__ __forceinline__ void gemm_tn(const float* A, const float* B, int row0, int c0,
                                        float acc[2][4]) {
#pragma unroll 8
    for (int cc = 0; cc < 64; cc++) {
        float4 bv = *(const float4*)&B[cc * 64 + c0];
        float a0 = A[cc * 64 + row0];
        float a1 = A[cc * 64 + row0 + 1];
        acc[0][0] += a0 * bv.x; acc[0][1] += a0 * bv.y;
        acc[0][2] += a0 * bv.z; acc[0][3] += a0 * bv.w;
        acc[1][0] += a1 * bv.x; acc[1][1] += a1 * bv.y;
        acc[1][2] += a1 * bv.z; acc[1][3] += a1 * bv.w;
    }
}

__global__ void k23_attn(const float* __restrict__ Wq, const float* __restrict__ Wk,
                         const float* __restrict__ rescale, const float* __restrict__ Wproj,
                         const float* __restrict__ Wv) {
    extern __shared__ float sm[];
    float* sA = sm;
    float* sB = sm + 4096;
    float* sC = sm + 8192;
    float* sD = sm + 12288;
    float* n2 = sm + 16384;   // [0:64) nq^2, [64:128) nk^2
    float* nrm = sm + 16512;
    int blk = blockIdx.x, b = blk >> 3, h = blk & 7;
    int tid = threadIdx.x;
    int row0 = (tid >> 4) * 2;
    int c0 = (tid & 15) * 4;

    for (int u = tid; u < 4096; u += 512) {
        int cc = u >> 6, j = u & 63;
        sA[u] = g_S[b * 4096 + u];
        sB[u] = Wq[cc * HD + h * 64 + j];
        sC[u] = Wk[cc * HD + h * 64 + j];
    }
    if (tid < 128) n2[tid] = 0.f;
    __syncthreads();
    float resc = rescale[h];

    // GEMM1: sD = S @ Wq
    float acc1[2][4];
#pragma unroll
    for (int r = 0; r < 2; r++)
#pragma unroll
        for (int s = 0; s < 4; s++) acc1[r][s] = 0.f;
    gemm_nn(sA, sB, row0, c0, acc1);
#pragma unroll
    for (int r = 0; r < 2; r++)
        *(float4*)&sD[(row0 + r) * 64 + c0] =
            make_float4(acc1[r][0], acc1[r][1], acc1[r][2], acc1[r][3]);
    __syncthreads();

    // nq partial (Wq . SQ) + GEMM2 (SK)
    {
        int j = tid & 63, cp = tid >> 6;
        float p = 0.f;
#pragma unroll
        for (int k = 0; k < 8; k++) {
            int c = cp * 8 + k;
            p += sB[c * 64 + j] * sD[c * 64 + j];
        }
        atomicAdd(&n2[j], p);
    }
    float acc2[2][4];
#pragma unroll
    for (int r = 0; r < 2; r++)
#pragma unroll
        for (int s = 0; s < 4; s++) acc2[r][s] = 0.f;
    gemm_nn(sA, sC, row0, c0, acc2);
    __syncthreads();
#pragma unroll
    for (int r = 0; r < 2; r++)
        *(float4*)&sB[(row0 + r) * 64 + c0] =
            make_float4(acc2[r][0], acc2[r][1], acc2[r][2], acc2[r][3]);   // sB = SK
    __syncthreads();

    // nk partial (Wk . SK)
    {
        int i = tid & 63, cp = tid >> 6;
        float p = 0.f;
#pragma unroll
        for (int k = 0; k < 8; k++) {
            int c = cp * 8 + k;
            p += sC[c * 64 + i] * sB[c * 64 + i];
        }
        atomicAdd(&n2[64 + i], p);
    }
    __syncthreads();
    if (tid < 128) nrm[tid] = fmaxf(sqrtf(fmaxf(n2[tid], 0.f)), 1e-12f);

    // GEMM3: G[i][j] = sum_c Wk[c][i] * SQ[c][j]; load Wproj into sB (SK dead)
    float acc3[2][4];
#pragma unroll
    for (int r = 0; r < 2; r++)
#pragma unroll
        for (int s = 0; s < 4; s++) acc3[r][s] = 0.f;
    gemm_tn(sC, sD, row0, c0, acc3);
    for (int u = tid; u < 4096; u += 512) sB[u] = Wproj[h * 4096 + u];
    __syncthreads();
#pragma unroll
    for (int r = 0; r < 2; r++) {
        float ri = resc / nrm[64 + row0 + r];
#pragma unroll
        for (int s = 0; s < 4; s++)
            sA[(row0 + r) * 64 + c0 + s] = acc3[r][s] * ri / nrm[c0 + s];
    }
    __syncthreads();

    // parallel softmax over rows of sA (8 threads/row)
    {
        int row = tid >> 3, g = tid & 7;
        float4 v0 = *(const float4*)&sA[row * 64 + g * 8];
        float4 v1 = *(const float4*)&sA[row * 64 + g * 8 + 4];
        float m = fmaxf(fmaxf(fmaxf(v0.x, v0.y), fmaxf(v0.z, v0.w)),
                        fmaxf(fmaxf(v1.x, v1.y), fmaxf(v1.z, v1.w)));
#pragma unroll
        for (int k = 1; k < 8; k <<= 1) m = fmaxf(m, __shfl_xor_sync(0xffffffffu, m, k, 8));
        v0.x = expf(v0.x - m); v0.y = expf(v0.y - m); v0.z = expf(v0.z - m); v0.w = expf(v0.w - m);
        v1.x = expf(v1.x - m); v1.y = expf(v1.y - m); v1.z = expf(v1.z - m); v1.w = expf(v1.w - m);
        float ssum = v0.x + v0.y + v0.z + v0.w + v1.x + v1.y + v1.z + v1.w;
#pragma unroll
        for (int k = 1; k < 8; k <<= 1) ssum += __shfl_xor_sync(0xffffffffu, ssum, k, 8);
        float inv = 1.f / ssum;
        v0.x *= inv; v0.y *= inv; v0.z *= inv; v0.w *= inv;
        v1.x *= inv; v1.y *= inv; v1.z *= inv; v1.w *= inv;
        *(float4*)&sA[row * 64 + g * 8] = v0;
        *(float4*)&sA[row * 64 + g * 8 + 4] = v1;
    }
    __syncthreads();

    // GEMM4: B[j][d] = sum_i attn[i][j] * Wproj[i][d] -> sD ; load Wv into sC
    float acc4[2][4];
#pragma unroll
    for (int r = 0; r < 2; r++)
#pragma unroll
        for (int s = 0; s < 4; s++) acc4[r][s] = 0.f;
    gemm_tn(sA, sB, row0, c0, acc4);
#pragma unroll
    for (int r = 0; r < 2; r++)
        *(float4*)&sD[(row0 + r) * 64 + c0] =
            make_float4(acc4[r][0], acc4[r][1], acc4[r][2], acc4[r][3]);
    for (int u = tid; u < 4096; u += 512) sC[u] = Wv[(u >> 6) * HD + h * 64 + (u & 63)];
    __syncthreads();

    // GEMM5: M[c][d] = sum_j Wv[c][j] * B[j][d] -> atomic g_M
    float acc5[2][4];
#pragma unroll
    for (int r = 0; r < 2; r++)
#pragma unroll
        for (int s = 0; s < 4; s++) acc5[r][s] = 0.f;
    gemm_nn(sC, sD, row0, c0, acc5);
#pragma unroll
    for (int r = 0; r < 2; r++)
#pragma unroll
        for (int s = 0; s < 4; s++)
            atomicAdd(&g_M[b * 4096 + (row0 + r) * 64 + c0 + s], acc5[r][s]);
}

// ---------------- K4a: p_pre = x @ Wp + bc1d -> g_P ----------------
// grid 1024, 256 thr, 128 px/block; 4px x 8ch register blocking; xs rows padded to 68
#define XSP 68
__global__ void k4a_P(const float* __restrict__ x, const float* __restrict__ bc1d) {
    extern __shared__ float sm[];
    float* Wps = sm;            // 4096
    float* xs  = sm + 4096;     // 128*68 = 8704
    float* bc  = sm + 12800;    // 64
    int tid = threadIdx.x;
    size_t base = (size_t)blockIdx.x * 8192;
    const float4* src = (const float4*)(x + base);
    for (int u = tid; u < 2048; u += 256) {
        int p = u >> 4, c4 = (u & 15) * 4;
        *(float4*)&xs[p * XSP + c4] = src[u];
    }
    for (int u = tid; u < 1024; u += 256) ((float4*)Wps)[u] = ((const float4*)g_Wp)[u];
    if (tid < 64) bc[tid] = bc1d[tid];
    __syncthreads();

    int pg = tid >> 3;          // 0..31 -> pixels 4pg..4pg+3
    int cg = (tid & 7) * 8;     // 8 channels
    float acc[4][8];
#pragma unroll
    for (int r = 0; r < 4; r++)
#pragma unroll
        for (int s = 0; s < 8; s++) acc[r][s] = 0.f;
#pragma unroll
    for (int cc4 = 0; cc4 < 64; cc4 += 4) {
        float4 bA[4], bB[4];
#pragma unroll
        for (int c = 0; c < 4; c++) {
            bA[c] = *(const float4*)&Wps[(cc4 + c) * 64 + cg];
            bB[c] = *(const float4*)&Wps[(cc4 + c) * 64 + cg + 4];
        }
#pragma unroll
        for (int r = 0; r < 4; r++) {
            float4 a = *(const float4*)&xs[(4 * pg + r) * XSP + cc4];
            mk44(a, bA[0], bA[1], bA[2], bA[3], &acc[r][0]);
            mk44(a, bB[0], bB[1], bB[2], bB[3], &acc[r][4]);
        }
    }
    float4 bc0 = *(const float4*)&bc[cg];
    float4 bc1 = *(const float4*)&bc[cg + 4];
#pragma unroll
    for (int r = 0; r < 4; r++) {
        int p = 4 * pg + r;
        float4 o0 = make_float4(acc[r][0] + bc0.x, acc[r][1] + bc0.y,
                                acc[r][2] + bc0.z, acc[r][3] + bc0.w);
        float4 o1 = make_float4(acc[r][4] + bc1.x, acc[r][5] + bc1.y,
                                acc[r][6] + bc1.z, acc[r][7] + bc1.w);
        *(float4*)&g_P[base + (size_t)p * 64 + cg] = o0;
        *(float4*)&g_P[base + (size_t)p * 64 + cg + 4] = o1;
    }
}

// ---------------- K4b: conv1+GELU+conv2 + x@M + bproj -> out (grid 2048, 256 thr) ----------------
// smem 16832 floats (67.3 KB): xs/Ms aliased into ps region after conv1 -> 3 blocks/SM
__device__ __forceinline__ float gelu_f(float a) {
    return 0.5f * a * (1.f + erff(a * 0.70710678118654752f));
}

__global__ void k4b_main(const float* __restrict__ x, const float* __restrict__ bproj,
                         const float* __restrict__ Wpe1, const float* __restrict__ Wpe2,
                         float* __restrict__ out) {
    extern __shared__ float sm4[];
    float* ps  = sm4;            // 12x12x64 = 9216 (phases 1-2)
    float* p1  = sm4 + 9216;     // 10x10x64 = 6400
    float* w1t = sm4 + 15616;    // 576  (transposed: [k][c])
    float* w2s = sm4 + 16192;    // 576  (original:   [c][k])
    float* bps = sm4 + 16768;    // 64
    float* xs  = sm4;            // 4096 (phase 3, aliases ps)
    float* Ms  = sm4 + 4096;     // 4096 (phase 3, aliases ps)
    int blk = blockIdx.x;
    int b = blk >> 10;
    int rem = blk & 1023;
    int y0 = (rem >> 5) * 8, x0 = (rem & 31) * 8;
    int tid = threadIdx.x;

    for (int u = tid; u < 576; u += 256) {
        int c = u / 9, k = u - c * 9;
        w1t[k * 64 + c] = Wpe1[u];
        w2s[u] = Wpe2[u];
    }
    if (tid < 64) bps[tid] = bproj[tid];
    for (int u = tid; u < 2304; u += 256) {   // halo p_pre (float4)
        int pidx = u >> 4, cgh = (u & 15) * 4;
        int py = pidx / 12, pxx = pidx - py * 12;
        int gy = y0 - 2 + py, gx = x0 - 2 + pxx;
        float4 v = make_float4(0.f, 0.f, 0.f, 0.f);
        if ((unsigned)gy < HH && (unsigned)gx < WW)
            v = *(const float4*)&g_P[(((size_t)(b * HH + gy)) * WW + gx) * 64 + cgh];
        *(float4*)&ps[pidx * 64 + cgh] = v;
    }
    __syncthreads();

    // conv1 + GELU: each thread has a FIXED channel group -> hoist weights to regs
    {
        int cgc = (tid & 15) * 4;
        float4 wv1[9];
#pragma unroll
        for (int k = 0; k < 9; k++) wv1[k] = *(const float4*)&w1t[k * 64 + cgc];
        for (int u = tid; u < 1600; u += 256) {
            int pidx = u >> 4;
            int py = pidx / 10, pxx = pidx - py * 10;
            int gy = y0 - 1 + py, gx = x0 - 1 + pxx;
            float4 a = make_float4(0.f, 0.f, 0.f, 0.f);
            if ((unsigned)gy < HH && (unsigned)gx < WW) {
#pragma unroll
                for (int ky = 0; ky < 3; ky++)
#pragma unroll
                    for (int kx = 0; kx < 3; kx++) {
                        int k = ky * 3 + kx;
                        float4 pv = *(const float4*)&ps[((py + ky) * 12 + pxx + kx) * 64 + cgc];
                        a.x += pv.x * wv1[k].x; a.y += pv.y * wv1[k].y;
                        a.z += pv.z * wv1[k].z; a.w += pv.w * wv1[k].w;
                    }
                a.x = gelu_f(a.x); a.y = gelu_f(a.y); a.z = gelu_f(a.z); a.w = gelu_f(a.w);
            }
            *(float4*)&p1[pidx * 64 + cgc] = a;
        }
    }
    __syncthreads();   // ps dead from here; xs/Ms reuse its space

    for (int u = tid; u < 1024; u += 256) {    // xs <- x tile
        int py = u >> 7, off = u & 127;
        const float4* src = (const float4*)(x + (((size_t)(b * HH + y0 + py)) * WW + x0) * 64);
        ((float4*)xs)[py * 128 + off] = src[off];
    }
    for (int u = tid; u < 1024; u += 256)      // Ms <- g_M[b]
        ((float4*)Ms)[u] = ((const float4*)(g_M + b * 4096))[u];
    __syncthreads();

    int ti = tid >> 4, tj = tid & 15;
    float wr[4][9];
#pragma unroll
    for (int s = 0; s < 4; s++)
#pragma unroll
        for (int k = 0; k < 9; k++) wr[s][k] = w2s[(4 * tj + s) * 9 + k];

    float acc[4][4];
#pragma unroll
    for (int r = 0; r < 4; r++)
#pragma unroll
        for (int s = 0; s < 4; s++) acc[r][s] = 0.f;
#pragma unroll
    for (int cc4 = 0; cc4 < 64; cc4 += 4) {   // x @ M (vectorized)
        float4 b0 = *(const float4*)&Ms[(cc4 + 0) * 64 + 4 * tj];
        float4 b1 = *(const float4*)&Ms[(cc4 + 1) * 64 + 4 * tj];
        float4 b2 = *(const float4*)&Ms[(cc4 + 2) * 64 + 4 * tj];
        float4 b3 = *(const float4*)&Ms[(cc4 + 3) * 64 + 4 * tj];
#pragma unroll
        for (int r = 0; r < 4; r++) {
            float4 ar = *(const float4*)&xs[(4 * ti + r) * 64 + cc4];
            mk44(ar, b0, b1, b2, b3, acc[r]);
        }
    }
#pragma unroll
    for (int r = 0; r < 4; r++) {             // conv2 + combine + store
        int pl = 4 * ti + r, py = pl >> 3, pxx = pl & 7;
        float cv[4] = {0.f, 0.f, 0.f, 0.f};
#pragma unroll
        for (int ky = 0; ky < 3; ky++)
#pragma unroll
            for (int kx = 0; kx < 3; kx++) {
                int k = ky * 3 + kx;
                float4 pv = *(const float4*)&p1[((py + ky) * 10 + pxx + kx) * 64 + 4 * tj];
                cv[0] += pv.x * wr[0][k];
                cv[1] += pv.y * wr[1][k];
                cv[2] += pv.z * wr[2][k];
                cv[3] += pv.w * wr[3][k];
            }
        float4 o;
        o.x = acc[r][0] + cv[0] + bps[4 * tj + 0];
        o.y = acc[r][1] + cv[1] + bps[4 * tj + 1];
        o.z = acc[r][2] + cv[2] + bps[4 * tj + 2];
        o.w = acc[r][3] + cv[3] + bps[4 * tj + 3];
        *(float4*)(out + (((size_t)(b * HH + y0 + py)) * WW + x0 + pxx) * 64 + 4 * tj) = o;
    }
}

// ---------------- launch ----------------
extern "C" void kernel_launch(void* const* d_in, const int* in_sizes, int n_in,
                              void* d_out, int out_size) {
    const float* x     = (const float*)d_in[0];
    const float* Wq    = (const float*)d_in[1];
    const float* Wk    = (const float*)d_in[2];
    const float* Wv    = (const float*)d_in[3];
    const float* resc  = (const float*)d_in[4];
    const float* Wproj = (const float*)d_in[5];
    const float* bproj = (const float*)d_in[6];
    const float* Wc1d  = (const float*)d_in[7];
    const float* bc1d  = (const float*)d_in[8];
    const float* Wpe1  = (const float*)d_in[9];
    const float* Wpe2  = (const float*)d_in[10];
    float* out = (float*)d_out;

    // one-time infra (created on the first, non-captured correctness call)
    static cudaStream_t s_aux = [] {
        cudaStream_t s; cudaStreamCreateWithFlags(&s, cudaStreamNonBlocking); return s;
    }();
    static cudaEvent_t ev_fork = [] {
        cudaEvent_t e; cudaEventCreateWithFlags(&e, cudaEventDisableTiming); return e;
    }();
    static cudaEvent_t ev_join = [] {
        cudaEvent_t e; cudaEventCreateWithFlags(&e, cudaEventDisableTiming); return e;
    }();

    cudaFuncSetAttribute(k23_attn, cudaFuncAttributeMaxDynamicSharedMemorySize, 16640 * 4);
    cudaFuncSetAttribute(k4a_P, cudaFuncAttributeMaxDynamicSharedMemorySize, 12864 * 4);
    cudaFuncSetAttribute(k4b_main, cudaFuncAttributeMaxDynamicSharedMemorySize, 16832 * 4);

    // fork: aux branch runs zero + S gram + attention -> g_M
    cudaEventRecord(ev_fork, 0);
    cudaStreamWaitEvent(s_aux, ev_fork, 0);
    k0_zero<<<8, 1024, 0, s_aux>>>();
    k1_S<<<128, 256, 0, s_aux>>>(x);
    k23_attn<<<16, 512, 16640 * 4, s_aux>>>(Wq, Wk, resc, Wproj, Wv);
    cudaEventRecord(ev_join, s_aux);

    // main branch: Wp (direct, no deps) then big P GEMM
    kWp<<<16, 256>>>(Wv, Wc1d);
    k4a_P<<<1024, 256, 12864 * 4>>>(x, bc1d);

    cudaStreamWaitEvent(0, ev_join, 0);
    k4b_main<<<2048, 256, 16832 * 4>>>(x, bproj, Wpe1, Wpe2, out);
}